// round 13
// baseline (speedup 1.0000x reference)
#include <cuda_runtime.h>
#include <cuda_bf16.h>
#include <cstdint>

#define BATCH 8
#define SEQ   1024
#define DIM   768
#define NHEAD 12
#define HDIM  64
#define BH    (BATCH * NHEAD)     // 96
#define MROWS (BATCH * SEQ)       // 8192
#define OUT_OFF ((size_t)MROWS * DIM)

// ---------------- scratch (__device__ globals; no allocs allowed) ----------
__device__ __nv_bfloat16 g_Xh[MROWS * DIM];
__device__ __nv_bfloat16 g_Xl[MROWS * DIM];
__device__ __nv_bfloat16 g_Qh[MROWS * DIM];
__device__ __nv_bfloat16 g_Ql[MROWS * DIM];
__device__ __nv_bfloat16 g_Kh[MROWS * DIM];
__device__ __nv_bfloat16 g_Kl[MROWS * DIM];
__device__ __nv_bfloat16 g_VTh[BH * HDIM * SEQ];  // [bh*64+d][n]
__device__ __nv_bfloat16 g_VTl[BH * HDIM * SEQ];
__device__ __nv_bfloat16 g_Oh[MROWS * DIM];
__device__ __nv_bfloat16 g_Ol[MROWS * DIM];
__device__ __nv_bfloat16 g_WTh[4 * DIM * DIM];    // W^T hi: [q;k;v;o] rows
__device__ __nv_bfloat16 g_WTl[4 * DIM * DIM];

// ---------------- helpers --------------------------------------------------
__device__ __forceinline__ uint32_t smem_u32(const void* p) {
    uint32_t a;
    asm("{ .reg .u64 t; cvta.to.shared.u64 t, %1; cvt.u32.u64 %0, t; }"
        : "=r"(a) : "l"(p));
    return a;
}
#define CP_ASYNC16(sm, gp) \
    asm volatile("cp.async.cg.shared.global [%0], [%1], 16;" \
                 :: "r"(sm), "l"(gp) : "memory")
#define CP_COMMIT() asm volatile("cp.async.commit_group;" ::: "memory")
#define CP_WAIT1()  asm volatile("cp.async.wait_group 1;" ::: "memory")
#define CP_WAIT0()  asm volatile("cp.async.wait_group 0;" ::: "memory")
#define LDSM_X4(r0, r1, r2, r3, addr) \
    asm volatile("ldmatrix.sync.aligned.m8n8.x4.shared.b16 {%0,%1,%2,%3}, [%4];" \
                 : "=r"(r0), "=r"(r1), "=r"(r2), "=r"(r3) : "r"(addr))
#define LDSM_X2(r0, r1, addr) \
    asm volatile("ldmatrix.sync.aligned.m8n8.x2.shared.b16 {%0,%1}, [%2];" \
                 : "=r"(r0), "=r"(r1) : "r"(addr))
#define MMA16816(d, a, b) \
    asm volatile("mma.sync.aligned.m16n8k16.row.col.f32.bf16.bf16.f32 " \
                 "{%0,%1,%2,%3}, {%4,%5,%6,%7}, {%8,%9}, {%0,%1,%2,%3};" \
                 : "+f"((d)[0]), "+f"((d)[1]), "+f"((d)[2]), "+f"((d)[3]) \
                 : "r"((a)[0]), "r"((a)[1]), "r"((a)[2]), "r"((a)[3]), \
                   "r"((b)[0]), "r"((b)[1]))

__device__ __forceinline__ __nv_bfloat162 split_hi2(float a, float b,
                                                    __nv_bfloat162& lo) {
    __nv_bfloat16 h0 = __float2bfloat16(a);
    __nv_bfloat16 h1 = __float2bfloat16(b);
    lo.x = __float2bfloat16(a - __bfloat162float(h0));
    lo.y = __float2bfloat16(b - __bfloat162float(h1));
    __nv_bfloat162 hi; hi.x = h0; hi.y = h1;
    return hi;
}

// ---------------------------------------------------------------------------
__global__ void split_kernel(const float* __restrict__ src,
                             __nv_bfloat16* __restrict__ hi,
                             __nv_bfloat16* __restrict__ lo, int n4) {
    int i = blockIdx.x * blockDim.x + threadIdx.x;
    if (i >= n4) return;
    float4 v = reinterpret_cast<const float4*>(src)[i];
    __nv_bfloat162 l0, l1;
    __nv_bfloat162 h0 = split_hi2(v.x, v.y, l0);
    __nv_bfloat162 h1 = split_hi2(v.z, v.w, l1);
    reinterpret_cast<__nv_bfloat162*>(hi)[2 * i]     = h0;
    reinterpret_cast<__nv_bfloat162*>(hi)[2 * i + 1] = h1;
    reinterpret_cast<__nv_bfloat162*>(lo)[2 * i]     = l0;
    reinterpret_cast<__nv_bfloat162*>(lo)[2 * i + 1] = l1;
}

__global__ void splitT4(const float* __restrict__ W0, const float* __restrict__ W1,
                        const float* __restrict__ W2, const float* __restrict__ W3,
                        __nv_bfloat16* __restrict__ hiT,
                        __nv_bfloat16* __restrict__ loT) {
    __shared__ float t[32][33];
    int z = blockIdx.z;
    const float* W = (z == 0) ? W0 : (z == 1) ? W1 : (z == 2) ? W2 : W3;
    size_t zoff = (size_t)z * DIM * DIM;
    int n0 = blockIdx.x * 32, k0 = blockIdx.y * 32;
    int tx = threadIdx.x, ty = threadIdx.y;           // (32, 8)
    #pragma unroll
    for (int i = 0; i < 4; ++i)
        t[ty * 4 + i][tx] = W[(size_t)(k0 + ty * 4 + i) * DIM + n0 + tx];
    __syncthreads();
    #pragma unroll
    for (int i = 0; i < 4; ++i) {
        int n = n0 + ty * 4 + i, k = k0 + tx;
        float a = t[tx][ty * 4 + i];
        __nv_bfloat16 h = __float2bfloat16(a);
        hiT[zoff + (size_t)n * DIM + k] = h;
        loT[zoff + (size_t)n * DIM + k] = __float2bfloat16(a - __bfloat162float(h));
    }
}

// ---------------------------------------------------------------------------
// GEMM tiles (128x128x32, 8 warps 2x4, 3-stage, single-sync mainloop).
// ---------------------------------------------------------------------------
#define TILE_B   10240
#define STAGE_B  (4 * TILE_B)
#define GSMEM3   (3 * STAGE_B)         // 122880

__global__ __launch_bounds__(256, 1)
void gemm_qkv(const float* __restrict__ bq, const float* __restrict__ bk,
              const float* __restrict__ bv) {
    extern __shared__ char sm[];
    const int tid = threadIdx.x;
    const int lane = tid & 31;
    const int warp = tid >> 5;
    const int wm = warp >> 2, wn = warp & 3;
    const size_t row0 = (size_t)blockIdx.y * 128;
    const int bx = blockIdx.x;
    const int sel = bx / 6;
    const size_t col0g = (size_t)bx * 128;
    const int col0l = (bx - sel * 6) * 128;
    const uint32_t smb = smem_u32(sm);
    const float* bias = (sel == 0) ? bq : (sel == 1) ? bk : bv;

    float acc[4][4][4];
    #pragma unroll
    for (int i = 0; i < 4; ++i)
        #pragma unroll
        for (int j = 0; j < 4; ++j)
            #pragma unroll
            for (int q = 0; q < 4; ++q) acc[i][j][q] = 0.f;

    const int r_c0 = tid >> 2, j_c0 = tid & 3;
    const int r_c1 = (tid + 256) >> 2, j_c1 = (tid + 256) & 3;

    auto issue = [&](int s, int st) {
        const int k0 = s * 32;
        const uint32_t sb = smb + st * STAGE_B;
        uint32_t d0 = sb + r_c0 * 80 + j_c0 * 16;
        CP_ASYNC16(d0,            g_Xh + (row0 + r_c0) * DIM + k0 + j_c0 * 8);
        CP_ASYNC16(d0 + TILE_B,   g_Xl + (row0 + r_c0) * DIM + k0 + j_c0 * 8);
        CP_ASYNC16(d0 + 2*TILE_B, g_WTh + (col0g + r_c0) * DIM + k0 + j_c0 * 8);
        CP_ASYNC16(d0 + 3*TILE_B, g_WTl + (col0g + r_c0) * DIM + k0 + j_c0 * 8);
        uint32_t d1 = sb + r_c1 * 80 + j_c1 * 16;
        CP_ASYNC16(d1,            g_Xh + (row0 + r_c1) * DIM + k0 + j_c1 * 8);
        CP_ASYNC16(d1 + TILE_B,   g_Xl + (row0 + r_c1) * DIM + k0 + j_c1 * 8);
        CP_ASYNC16(d1 + 2*TILE_B, g_WTh + (col0g + r_c1) * DIM + k0 + j_c1 * 8);
        CP_ASYNC16(d1 + 3*TILE_B, g_WTl + (col0g + r_c1) * DIM + k0 + j_c1 * 8);
        CP_COMMIT();
    };

    const int a_row_l = (lane & 15);
    const int a_col_l = (lane >> 4) << 3;
    const int b_row_l = (lane & 7) + ((lane >> 4) << 3);
    const int b_col_l = ((lane >> 3) & 1) << 3;

    issue(0, 0); issue(1, 1);
    for (int s = 0; s < 24; ++s) {
        if (s < 23) CP_WAIT1(); else CP_WAIT0();
        __syncthreads();
        if (s + 2 < 24) issue(s + 2, (s + 2) % 3);
        const uint32_t sb = smb + (s % 3) * STAGE_B;
        const uint32_t tAh = sb, tAl = sb + TILE_B;
        const uint32_t tBh = sb + 2 * TILE_B, tBl = sb + 3 * TILE_B;
        #pragma unroll
        for (int ks = 0; ks < 2; ++ks) {
            uint32_t ah[4][4], al[4][4], bh[4][2], bl[4][2];
            #pragma unroll
            for (int mi = 0; mi < 4; ++mi) {
                uint32_t off = (uint32_t)((wm * 64 + mi * 16 + a_row_l) * 80 +
                                          (ks * 16 + a_col_l) * 2);
                LDSM_X4(ah[mi][0], ah[mi][1], ah[mi][2], ah[mi][3], tAh + off);
                LDSM_X4(al[mi][0], al[mi][1], al[mi][2], al[mi][3], tAl + off);
            }
            #pragma unroll
            for (int nj = 0; nj < 2; ++nj) {
                uint32_t off = (uint32_t)((wn * 32 + nj * 16 + b_row_l) * 80 +
                                          (ks * 16 + b_col_l) * 2);
                uint32_t t0, t1, t2, t3;
                LDSM_X4(t0, t1, t2, t3, tBh + off);
                bh[nj * 2][0] = t0; bh[nj * 2][1] = t1;
                bh[nj * 2 + 1][0] = t2; bh[nj * 2 + 1][1] = t3;
                LDSM_X4(t0, t1, t2, t3, tBl + off);
                bl[nj * 2][0] = t0; bl[nj * 2][1] = t1;
                bl[nj * 2 + 1][0] = t2; bl[nj * 2 + 1][1] = t3;
            }
            #pragma unroll
            for (int mi = 0; mi < 4; ++mi)
                #pragma unroll
                for (int ni = 0; ni < 4; ++ni) {
                    MMA16816(acc[mi][ni], ah[mi], bh[ni]);
                    MMA16816(acc[mi][ni], al[mi], bh[ni]);
                    MMA16816(acc[mi][ni], ah[mi], bl[ni]);
                }
        }
    }

    __nv_bfloat16* Ch = (sel == 0) ? g_Qh : g_Kh;
    __nv_bfloat16* Cl = (sel == 0) ? g_Ql : g_Kl;
    const int mbase = (int)row0 + wm * 64;
    const int nbase = col0l + wn * 32;
    #pragma unroll
    for (int mi = 0; mi < 4; ++mi) {
        #pragma unroll
        for (int ni = 0; ni < 4; ++ni) {
            int r = mbase + mi * 16 + (lane >> 2);
            int c = nbase + ni * 8 + (lane & 3) * 2;
            float b0 = bias[c], b1 = bias[c + 1];
            float v00 = acc[mi][ni][0] + b0, v01 = acc[mi][ni][1] + b1;
            float v10 = acc[mi][ni][2] + b0, v11 = acc[mi][ni][3] + b1;
            if (sel < 2) {
                __nv_bfloat162 lo0, lo1;
                __nv_bfloat162 hi0 = split_hi2(v00, v01, lo0);
                __nv_bfloat162 hi1 = split_hi2(v10, v11, lo1);
                *(__nv_bfloat162*)&Ch[(size_t)r * DIM + c] = hi0;
                *(__nv_bfloat162*)&Cl[(size_t)r * DIM + c] = lo0;
                *(__nv_bfloat162*)&Ch[(size_t)(r + 8) * DIM + c] = hi1;
                *(__nv_bfloat162*)&Cl[(size_t)(r + 8) * DIM + c] = lo1;
            } else {
                int b = r >> 10, n = r & 1023;
                size_t row_c0 = ((size_t)b * NHEAD + (c >> 6)) * HDIM + (c & 63);
                size_t row_c1 = ((size_t)b * NHEAD + ((c + 1) >> 6)) * HDIM + ((c + 1) & 63);
                __nv_bfloat16 h, l;
                h = __float2bfloat16(v00); l = __float2bfloat16(v00 - __bfloat162float(h));
                g_VTh[row_c0 * SEQ + n] = h; g_VTl[row_c0 * SEQ + n] = l;
                h = __float2bfloat16(v01); l = __float2bfloat16(v01 - __bfloat162float(h));
                g_VTh[row_c1 * SEQ + n] = h; g_VTl[row_c1 * SEQ + n] = l;
                h = __float2bfloat16(v10); l = __float2bfloat16(v10 - __bfloat162float(h));
                g_VTh[row_c0 * SEQ + n + 8] = h; g_VTl[row_c0 * SEQ + n + 8] = l;
                h = __float2bfloat16(v11); l = __float2bfloat16(v11 - __bfloat162float(h));
                g_VTh[row_c1 * SEQ + n + 8] = h; g_VTl[row_c1 * SEQ + n + 8] = l;
            }
        }
    }
}

__global__ __launch_bounds__(256, 1)
void gemm_oproj(const __nv_bfloat16* __restrict__ Ah,
                const __nv_bfloat16* __restrict__ Al,
                const __nv_bfloat16* __restrict__ Bh,
                const __nv_bfloat16* __restrict__ Bl,
                const float* __restrict__ bias, float* __restrict__ Cf) {
    extern __shared__ char sm[];
    const int tid = threadIdx.x;
    const int lane = tid & 31;
    const int warp = tid >> 5;
    const int wm = warp >> 2, wn = warp & 3;
    const size_t row0 = (size_t)blockIdx.y * 128;
    const size_t col0 = (size_t)blockIdx.x * 128;
    const uint32_t smb = smem_u32(sm);

    float acc[4][4][4];
    #pragma unroll
    for (int i = 0; i < 4; ++i)
        #pragma unroll
        for (int j = 0; j < 4; ++j)
            #pragma unroll
            for (int q = 0; q < 4; ++q) acc[i][j][q] = 0.f;

    const int r_c0 = tid >> 2, j_c0 = tid & 3;
    const int r_c1 = (tid + 256) >> 2, j_c1 = (tid + 256) & 3;

    auto issue = [&](int s, int st) {
        const int k0 = s * 32;
        const uint32_t sb = smb + st * STAGE_B;
        uint32_t d0 = sb + r_c0 * 80 + j_c0 * 16;
        CP_ASYNC16(d0,            Ah + (row0 + r_c0) * DIM + k0 + j_c0 * 8);
        CP_ASYNC16(d0 + TILE_B,   Al + (row0 + r_c0) * DIM + k0 + j_c0 * 8);
        CP_ASYNC16(d0 + 2*TILE_B, Bh + (col0 + r_c0) * DIM + k0 + j_c0 * 8);
        CP_ASYNC16(d0 + 3*TILE_B, Bl + (col0 + r_c0) * DIM + k0 + j_c0 * 8);
        uint32_t d1 = sb + r_c1 * 80 + j_c1 * 16;
        CP_ASYNC16(d1,            Ah + (row0 + r_c1) * DIM + k0 + j_c1 * 8);
        CP_ASYNC16(d1 + TILE_B,   Al + (row0 + r_c1) * DIM + k0 + j_c1 * 8);
        CP_ASYNC16(d1 + 2*TILE_B, Bh + (col0 + r_c1) * DIM + k0 + j_c1 * 8);
        CP_ASYNC16(d1 + 3*TILE_B, Bl + (col0 + r_c1) * DIM + k0 + j_c1 * 8);
        CP_COMMIT();
    };

    const int a_row_l = (lane & 15);
    const int a_col_l = (lane >> 4) << 3;
    const int b_row_l = (lane & 7) + ((lane >> 4) << 3);
    const int b_col_l = ((lane >> 3) & 1) << 3;

    issue(0, 0); issue(1, 1);
    for (int s = 0; s < 24; ++s) {
        if (s < 23) CP_WAIT1(); else CP_WAIT0();
        __syncthreads();
        if (s + 2 < 24) issue(s + 2, (s + 2) % 3);
        const uint32_t sb = smb + (s % 3) * STAGE_B;
        const uint32_t tAh = sb, tAl = sb + TILE_B;
        const uint32_t tBh = sb + 2 * TILE_B, tBl = sb + 3 * TILE_B;
        #pragma unroll
        for (int ks = 0; ks < 2; ++ks) {
            uint32_t ah[4][4], al[4][4], bh[4][2], bl[4][2];
            #pragma unroll
            for (int mi = 0; mi < 4; ++mi) {
                uint32_t off = (uint32_t)((wm * 64 + mi * 16 + a_row_l) * 80 +
                                          (ks * 16 + a_col_l) * 2);
                LDSM_X4(ah[mi][0], ah[mi][1], ah[mi][2], ah[mi][3], tAh + off);
                LDSM_X4(al[mi][0], al[mi][1], al[mi][2], al[mi][3], tAl + off);
            }
            #pragma unroll
            for (int nj = 0; nj < 2; ++nj) {
                uint32_t off = (uint32_t)((wn * 32 + nj * 16 + b_row_l) * 80 +
                                          (ks * 16 + b_col_l) * 2);
                uint32_t t0, t1, t2, t3;
                LDSM_X4(t0, t1, t2, t3, tBh + off);
                bh[nj * 2][0] = t0; bh[nj * 2][1] = t1;
                bh[nj * 2 + 1][0] = t2; bh[nj * 2 + 1][1] = t3;
                LDSM_X4(t0, t1, t2, t3, tBl + off);
                bl[nj * 2][0] = t0; bl[nj * 2][1] = t1;
                bl[nj * 2 + 1][0] = t2; bl[nj * 2 + 1][1] = t3;
            }
            #pragma unroll
            for (int mi = 0; mi < 4; ++mi)
                #pragma unroll
                for (int ni = 0; ni < 4; ++ni) {
                    MMA16816(acc[mi][ni], ah[mi], bh[ni]);
                    MMA16816(acc[mi][ni], al[mi], bh[ni]);
                    MMA16816(acc[mi][ni], ah[mi], bl[ni]);
                }
        }
    }

    const int mbase = (int)row0 + wm * 64;
    const int nbase = (int)col0 + wn * 32;
    #pragma unroll
    for (int mi = 0; mi < 4; ++mi) {
        #pragma unroll
        for (int ni = 0; ni < 4; ++ni) {
            int r = mbase + mi * 16 + (lane >> 2);
            int c = nbase + ni * 8 + (lane & 3) * 2;
            float b0 = bias[c], b1 = bias[c + 1];
            *(float2*)&Cf[(size_t)r * DIM + c] =
                make_float2(acc[mi][ni][0] + b0, acc[mi][ni][1] + b1);
            *(float2*)&Cf[(size_t)(r + 8) * DIM + c] =
                make_float2(acc[mi][ni][2] + b0, acc[mi][ni][3] + b1);
        }
    }
}

// ---------------------------------------------------------------------------
// Fused attention: scores + softmax + weights-write + O = P @ V.
// 32-row tile per block, 512 threads. Phase 1: 16 warps = 2 row-groups x 8
// col-owners compute S chunks in registers. Phase 2: per 128-col chunk,
// normalized P -> smem bf16 hi/lo, V chunk streamed (reusing K smem),
// accumulate O fragments; write weights fp32 + O bf16 hi/lo.
// ---------------------------------------------------------------------------
#define AF_QSZ   4608                 // 32 rows * 144 B
#define AF_Q0    0
#define AF_Q1    AF_QSZ               // 4608
#define AF_P0    0                    // phase 2 (overlaps dead Q)
#define AF_PCOMP 8704                 // 32 * 272
#define AF_K0    17408
#define AF_KSZ   18432                // 128 rows * 144 B
#define AF_V0    17408                // phase 2 (overlaps dead K)
#define AF_VCOMP 17408                // 64 * 272
#define AF_VSTG  34816                // hi + lo
#define AF_RED   91136                // after K region (17408 + 4*18432)
#define AF_SMEM  93184

__global__ __launch_bounds__(512, 1)
void attn_fused(float* __restrict__ Wt) {
    extern __shared__ char sm[];
    const uint32_t smb = smem_u32(sm);
    float* red_max = (float*)(sm + AF_RED);          // [32][8]
    float* red_sum = (float*)(sm + AF_RED + 1024);   // [32][8]
    const int tid = threadIdx.x;
    const int lane = tid & 31;
    const int warp = tid >> 5;                       // 0..15
    const int wg = warp >> 3;                        // row group 0/1
    const int wn = warp & 7;                         // col owner 0..7
    const int bh = blockIdx.y;
    const int b = bh / NHEAD, h = bh - b * NHEAD;
    const size_t i0 = (size_t)blockIdx.x * 32;
    const __nv_bfloat16* Qh = g_Qh + ((size_t)b * SEQ) * DIM + h * HDIM;
    const __nv_bfloat16* Ql = g_Ql + ((size_t)b * SEQ) * DIM + h * HDIM;
    const __nv_bfloat16* Kh = g_Kh + ((size_t)b * SEQ) * DIM + h * HDIM;
    const __nv_bfloat16* Kl = g_Kl + ((size_t)b * SEQ) * DIM + h * HDIM;
    const __nv_bfloat16* Vh = g_VTh + (size_t)bh * HDIM * SEQ;
    const __nv_bfloat16* Vl = g_VTl + (size_t)bh * HDIM * SEQ;

    float acc[8][2][4];
    #pragma unroll
    for (int c = 0; c < 8; ++c)
        #pragma unroll
        for (int j = 0; j < 2; ++j)
            #pragma unroll
            for (int q = 0; q < 4; ++q) acc[c][j][q] = 0.f;

    // Q: 32 rows x 128B hi+lo = 512 chunks; 1 per thread. K chunks 0,1.
    {
        int t = tid & 255;
        int r = t >> 3, j = t & 7;
        uint32_t d = smb + ((tid < 256) ? AF_Q0 : AF_Q1) + r * 144 + j * 16;
        const __nv_bfloat16* src = (tid < 256) ? Qh : Ql;
        CP_ASYNC16(d, src + (i0 + r) * DIM + j * 8);
        #pragma unroll
        for (int p = 0; p < 2; ++p) {
            int idx = tid + p * 512;
            int kr = idx >> 3, kj = idx & 7;
            uint32_t kd = smb + AF_K0 + kr * 144 + kj * 16;
            CP_ASYNC16(kd,          Kh + (size_t)kr * DIM + kj * 8);
            CP_ASYNC16(kd + AF_KSZ, Kl + (size_t)kr * DIM + kj * 8);
        }
        CP_COMMIT();
        #pragma unroll
        for (int p = 0; p < 2; ++p) {
            int idx = tid + p * 512;
            int kr = idx >> 3, kj = idx & 7;
            uint32_t kd = smb + AF_K0 + 2 * AF_KSZ + kr * 144 + kj * 16;
            CP_ASYNC16(kd,          Kh + (size_t)(128 + kr) * DIM + kj * 8);
            CP_ASYNC16(kd + AF_KSZ, Kl + (size_t)(128 + kr) * DIM + kj * 8);
        }
        CP_COMMIT();
    }

    const int a_row_l = (lane & 15);
    const int a_col_l = (lane >> 4) << 3;
    const int b_row_l = (lane & 7) + ((lane >> 4) << 3);
    const int b_col_l = ((lane >> 3) & 1) << 3;

    uint32_t qh[4][4], ql[4][4];
    bool qloaded = false;

    for (int c = 0; c < 8; ++c) {
        if (c < 7) CP_WAIT1(); else CP_WAIT0();
        __syncthreads();
        if (!qloaded) {
            #pragma unroll
            for (int ks = 0; ks < 4; ++ks) {
                uint32_t off = (uint32_t)((wg * 16 + a_row_l) * 144 +
                                          (ks * 16 + a_col_l) * 2);
                LDSM_X4(qh[ks][0], qh[ks][1], qh[ks][2], qh[ks][3],
                        smb + AF_Q0 + off);
                LDSM_X4(ql[ks][0], ql[ks][1], ql[ks][2], ql[ks][3],
                        smb + AF_Q1 + off);
            }
            qloaded = true;
        }
        const uint32_t kb = smb + AF_K0 + (c & 1) * 2 * AF_KSZ;
        #pragma unroll
        for (int ks = 0; ks < 4; ++ks) {
            uint32_t bh2[2][2], bl2[2][2];
            {
                uint32_t off = (uint32_t)((wn * 16 + b_row_l) * 144 +
                                          (ks * 16 + b_col_l) * 2);
                uint32_t t0, t1, t2, t3;
                LDSM_X4(t0, t1, t2, t3, kb + off);
                bh2[0][0] = t0; bh2[0][1] = t1;
                bh2[1][0] = t2; bh2[1][1] = t3;
                LDSM_X4(t0, t1, t2, t3, kb + AF_KSZ + off);
                bl2[0][0] = t0; bl2[0][1] = t1;
                bl2[1][0] = t2; bl2[1][1] = t3;
            }
            #pragma unroll
            for (int ni = 0; ni < 2; ++ni) {
                MMA16816(acc[c][ni], qh[ks], bh2[ni]);
                MMA16816(acc[c][ni], ql[ks], bh2[ni]);
                MMA16816(acc[c][ni], qh[ks], bl2[ni]);
            }
        }
        __syncthreads();
        if (c + 2 < 8) {
            const uint32_t kd0 = smb + AF_K0 + (c & 1) * 2 * AF_KSZ;
            const size_t j0n = (size_t)(c + 2) * 128;
            #pragma unroll
            for (int p = 0; p < 2; ++p) {
                int idx = tid + p * 512;
                int kr = idx >> 3, kj = idx & 7;
                uint32_t kd = kd0 + kr * 144 + kj * 16;
                CP_ASYNC16(kd,          Kh + (j0n + kr) * DIM + kj * 8);
                CP_ASYNC16(kd + AF_KSZ, Kl + (j0n + kr) * DIM + kj * 8);
            }
            CP_COMMIT();
        }
    }

    // ---- prefetch V chunks 0,1 (K region now dead) ----
    auto issueV = [&](int c, int st) {
        #pragma unroll
        for (int p = 0; p < 4; ++p) {
            int idx = tid + p * 512;             // 0..2047
            int comp = idx >> 10;                // 0=hi 1=lo
            int w2 = idx & 1023;
            int r = w2 >> 4, j = w2 & 15;
            const __nv_bfloat16* src = comp ? Vl : Vh;
            uint32_t d = smb + AF_V0 + st * AF_VSTG + comp * AF_VCOMP +
                         r * 272 + j * 16;
            CP_ASYNC16(d, src + (size_t)r * SEQ + c * 128 + j * 8);
        }
        CP_COMMIT();
    };
    issueV(0, 0);
    issueV(1, 1);

    // ---- softmax reductions (overlap with V prefetch) ----
    #pragma unroll
    for (int c = 0; c < 8; ++c)
        #pragma unroll
        for (int j = 0; j < 2; ++j)
            #pragma unroll
            for (int q = 0; q < 4; ++q) acc[c][j][q] *= 0.125f;

    const int R0 = wg * 16 + (lane >> 2);     // local rows 0..31
    const int R1 = R0 + 8;

    float m0 = -1e30f, m1 = -1e30f;
    #pragma unroll
    for (int c = 0; c < 8; ++c)
        #pragma unroll
        for (int j = 0; j < 2; ++j) {
            m0 = fmaxf(m0, fmaxf(acc[c][j][0], acc[c][j][1]));
            m1 = fmaxf(m1, fmaxf(acc[c][j][2], acc[c][j][3]));
        }
    m0 = fmaxf(m0, __shfl_xor_sync(~0u, m0, 1));
    m0 = fmaxf(m0, __shfl_xor_sync(~0u, m0, 2));
    m1 = fmaxf(m1, __shfl_xor_sync(~0u, m1, 1));
    m1 = fmaxf(m1, __shfl_xor_sync(~0u, m1, 2));
    if ((lane & 3) == 0) {
        red_max[R0 * 8 + wn] = m0;
        red_max[R1 * 8 + wn] = m1;
    }
    __syncthreads();
    m0 = red_max[R0 * 8];
    m1 = red_max[R1 * 8];
    #pragma unroll
    for (int i = 1; i < 8; ++i) {
        m0 = fmaxf(m0, red_max[R0 * 8 + i]);
        m1 = fmaxf(m1, red_max[R1 * 8 + i]);
    }

    float s0 = 0.f, s1 = 0.f;
    #pragma unroll
    for (int c = 0; c < 8; ++c)
        #pragma unroll
        for (int j = 0; j < 2; ++j) {
            acc[c][j][0] = __expf(acc[c][j][0] - m0);
            acc[c][j][1] = __expf(acc[c][j][1] - m0);
            acc[c][j][2] = __expf(acc[c][j][2] - m1);
            acc[c][j][3] = __expf(acc[c][j][3] - m1);
            s0 += acc[c][j][0] + acc[c][j][1];
            s1 += acc[c][j][2] + acc[c][j][3];
        }
    s0 += __shfl_xor_sync(~0u, s0, 1);
    s0 += __shfl_xor_sync(~0u, s0, 2);
    s1 += __shfl_xor_sync(~0u, s1, 1);
    s1 += __shfl_xor_sync(~0u, s1, 2);
    if ((lane & 3) == 0) {
        red_sum[R0 * 8 + wn] = s0;
        red_sum[R1 * 8 + wn] = s1;
    }
    __syncthreads();
    s0 = 0.f; s1 = 0.f;
    #pragma unroll
    for (int i = 0; i < 8; ++i) {
        s0 += red_sum[R0 * 8 + i];
        s1 += red_sum[R1 * 8 + i];
    }
    const float inv0 = 1.0f / s0, inv1 = 1.0f / s1;

    // ---- phase 2: per chunk, write weights, P->smem, O += P @ V ----
    float acc_o[4] = {0.f, 0.f, 0.f, 0.f};
    const int p_row = wg * 16 + a_row_l;
    const int v_row = wn * 8 + (lane & 7);
    const int v_col8 = ((lane >> 3) & 1) << 3;
    float* Wb = Wt + ((size_t)bh * SEQ + i0) * SEQ;

    for (int c = 0; c < 8; ++c) {
        // store normalized P chunk (bf16 hi/lo) + write fp32 weights
        #pragma unroll
        for (int j = 0; j < 2; ++j) {
            int col = wn * 16 + j * 8 + (lane & 3) * 2;    // 0..127 local
            float v00 = acc[c][j][0] * inv0, v01 = acc[c][j][1] * inv0;
            float v10 = acc[c][j][2] * inv1, v11 = acc[c][j][3] * inv1;
            *(float2*)&Wb[(size_t)R0 * SEQ + c * 128 + col] = make_float2(v00, v01);
            *(float2*)&Wb[(size_t)R1 * SEQ + c * 128 + col] = make_float2(v10, v11);
            __nv_bfloat162 lo0, lo1;
            __nv_bfloat162 hi0 = split_hi2(v00, v01, lo0);
            __nv_bfloat162 hi1 = split_hi2(v10, v11, lo1);
            uint32_t o0 = R0 * 272 + col * 2;
            uint32_t o1 = R1 * 272 + col * 2;
            *(__nv_bfloat162*)(sm + AF_P0 + o0) = hi0;
            *(__nv_bfloat162*)(sm + AF_P0 + AF_PCOMP + o0) = lo0;
            *(__nv_bfloat162*)(sm + AF_P0 + o1) = hi1;
            *(__nv_bfloat162*)(sm + AF_P0 + AF_PCOMP + o1) = lo1;
        }
        if (c < 7) CP_WAIT1(); else CP_WAIT0();
        __syncthreads();                       // P visible + V(c) arrived

        const uint32_t vb = smb + AF_V0 + (c & 1) * AF_VSTG;
        #pragma unroll
        for (int ks = 0; ks < 8; ++ks) {
            uint32_t aPh[4], aPl[4], bVh[2], bVl[2];
            uint32_t aoff = (uint32_t)(p_row * 272 + (ks * 16 + a_col_l) * 2);
            LDSM_X4(aPh[0], aPh[1], aPh[2], aPh[3], smb + AF_P0 + aoff);
            LDSM_X4(aPl[0], aPl[1], aPl[2], aPl[3],
                    smb + AF_P0 + AF_PCOMP + aoff);
            uint32_t boff = (uint32_t)(v_row * 272 + (ks * 16 + v_col8) * 2);
            LDSM_X2(bVh[0], bVh[1], vb + boff);
            LDSM_X2(bVl[0], bVl[1], vb + AF_VCOMP + boff);
            MMA16816(acc_o, aPh, bVh);
            MMA16816(acc_o, aPl, bVh);
            MMA16816(acc_o, aPh, bVl);
        }
        __syncthreads();                       // done reading P & V stage
        if (c + 2 < 8) issueV(c + 2, c & 1);
    }

    // ---- O epilogue: rows wg*16+(lane>>2)(+8), cols wn*8+(lane&3)*2 ----
    {
        size_t r = (size_t)b * SEQ + i0 + wg * 16 + (lane >> 2);
        size_t cg = (size_t)h * HDIM + wn * 8 + (lane & 3) * 2;
        __nv_bfloat162 lo0, lo1;
        __nv_bfloat162 hi0 = split_hi2(acc_o[0], acc_o[1], lo0);
        __nv_bfloat162 hi1 = split_hi2(acc_o[2], acc_o[3], lo1);
        *(__nv_bfloat162*)&g_Oh[r * DIM + cg] = hi0;
        *(__nv_bfloat162*)&g_Ol[r * DIM + cg] = lo0;
        *(__nv_bfloat162*)&g_Oh[(r + 8) * DIM + cg] = hi1;
        *(__nv_bfloat162*)&g_Ol[(r + 8) * DIM + cg] = lo1;
    }
}

// ---------------------------------------------------------------------------
extern "C" void kernel_launch(void* const* d_in, const int* in_sizes, int n_in,
                              void* d_out, int out_size) {
    const float* x  = (const float*)d_in[0];
    const float* Wq = (const float*)d_in[1];
    const float* bq = (const float*)d_in[2];
    const float* Wk = (const float*)d_in[3];
    const float* bk = (const float*)d_in[4];
    const float* Wv = (const float*)d_in[5];
    const float* bv = (const float*)d_in[6];
    const float* Wo = (const float*)d_in[7];
    const float* bo = (const float*)d_in[8];

    float* out = (float*)d_out;
    float* wts = out + OUT_OFF;

    cudaFuncSetAttribute(gemm_qkv,
                         cudaFuncAttributeMaxDynamicSharedMemorySize, GSMEM3);
    cudaFuncSetAttribute(gemm_oproj,
                         cudaFuncAttributeMaxDynamicSharedMemorySize, GSMEM3);
    cudaFuncSetAttribute(attn_fused,
                         cudaFuncAttributeMaxDynamicSharedMemorySize, AF_SMEM);

    __nv_bfloat16 *Xh, *Xl, *Oh, *Ol, *WTh, *WTl;
    cudaGetSymbolAddress((void**)&Xh, g_Xh);
    cudaGetSymbolAddress((void**)&Xl, g_Xl);
    cudaGetSymbolAddress((void**)&Oh, g_Oh);
    cudaGetSymbolAddress((void**)&Ol, g_Ol);
    cudaGetSymbolAddress((void**)&WTh, g_WTh);
    cudaGetSymbolAddress((void**)&WTl, g_WTl);

    const int NELEM = MROWS * DIM;
    split_kernel<<<NELEM / 4 / 256, 256>>>(x, Xh, Xl, NELEM / 4);
    splitT4<<<dim3(DIM / 32, DIM / 32, 4), dim3(32, 8)>>>(Wq, Wk, Wv, Wo,
                                                          WTh, WTl);

    gemm_qkv<<<dim3(18, MROWS / 128), 256, GSMEM3>>>(bq, bk, bv);

    attn_fused<<<dim3(SEQ / 32, BH), 512, AF_SMEM>>>(wts);

    gemm_oproj<<<dim3(DIM / 128, MROWS / 128), 256, GSMEM3>>>(
        Oh, Ol, WTh + 3 * DIM * DIM, WTl + 3 * DIM * DIM, bo, out);
}

// round 14
// speedup vs baseline: 1.1292x; 1.1292x over previous
#include <cuda_runtime.h>
#include <cuda_bf16.h>
#include <cstdint>

#define BATCH 8
#define SEQ   1024
#define DIM   768
#define NHEAD 12
#define HDIM  64
#define BH    (BATCH * NHEAD)     // 96
#define MROWS (BATCH * SEQ)       // 8192
#define OUT_OFF ((size_t)MROWS * DIM)

// ---------------- scratch (__device__ globals; no allocs allowed) ----------
__device__ __nv_bfloat16 g_Xh[MROWS * DIM];
__device__ __nv_bfloat16 g_Xl[MROWS * DIM];
__device__ __nv_bfloat16 g_Qh[MROWS * DIM];
__device__ __nv_bfloat16 g_Ql[MROWS * DIM];
__device__ __nv_bfloat16 g_Kh[MROWS * DIM];
__device__ __nv_bfloat16 g_Kl[MROWS * DIM];
__device__ __nv_bfloat16 g_VTh[BH * HDIM * SEQ];  // [bh*64+d][n]
__device__ __nv_bfloat16 g_VTl[BH * HDIM * SEQ];
__device__ __nv_bfloat16 g_Oh[MROWS * DIM];
__device__ __nv_bfloat16 g_Ol[MROWS * DIM];
__device__ __nv_bfloat16 g_WTh[4 * DIM * DIM];    // W^T hi: [q;k;v;o] rows
__device__ __nv_bfloat16 g_WTl[4 * DIM * DIM];

// ---------------- helpers --------------------------------------------------
__device__ __forceinline__ uint32_t smem_u32(const void* p) {
    uint32_t a;
    asm("{ .reg .u64 t; cvta.to.shared.u64 t, %1; cvt.u32.u64 %0, t; }"
        : "=r"(a) : "l"(p));
    return a;
}
#define CP_ASYNC16(sm, gp) \
    asm volatile("cp.async.cg.shared.global [%0], [%1], 16;" \
                 :: "r"(sm), "l"(gp) : "memory")
#define CP_COMMIT() asm volatile("cp.async.commit_group;" ::: "memory")
#define CP_WAIT1()  asm volatile("cp.async.wait_group 1;" ::: "memory")
#define CP_WAIT0()  asm volatile("cp.async.wait_group 0;" ::: "memory")
#define LDSM_X4(r0, r1, r2, r3, addr) \
    asm volatile("ldmatrix.sync.aligned.m8n8.x4.shared.b16 {%0,%1,%2,%3}, [%4];" \
                 : "=r"(r0), "=r"(r1), "=r"(r2), "=r"(r3) : "r"(addr))
#define MMA16816(d, a, b) \
    asm volatile("mma.sync.aligned.m16n8k16.row.col.f32.bf16.bf16.f32 " \
                 "{%0,%1,%2,%3}, {%4,%5,%6,%7}, {%8,%9}, {%0,%1,%2,%3};" \
                 : "+f"((d)[0]), "+f"((d)[1]), "+f"((d)[2]), "+f"((d)[3]) \
                 : "r"((a)[0]), "r"((a)[1]), "r"((a)[2]), "r"((a)[3]), \
                   "r"((b)[0]), "r"((b)[1]))

__device__ __forceinline__ __nv_bfloat162 split_hi2(float a, float b,
                                                    __nv_bfloat162& lo) {
    __nv_bfloat16 h0 = __float2bfloat16(a);
    __nv_bfloat16 h1 = __float2bfloat16(b);
    lo.x = __float2bfloat16(a - __bfloat162float(h0));
    lo.y = __float2bfloat16(b - __bfloat162float(h1));
    __nv_bfloat162 hi; hi.x = h0; hi.y = h1;
    return hi;
}

// ---------------------------------------------------------------------------
__global__ void split_kernel(const float* __restrict__ src,
                             __nv_bfloat16* __restrict__ hi,
                             __nv_bfloat16* __restrict__ lo, int n4) {
    int i = blockIdx.x * blockDim.x + threadIdx.x;
    if (i >= n4) return;
    float4 v = reinterpret_cast<const float4*>(src)[i];
    __nv_bfloat162 l0, l1;
    __nv_bfloat162 h0 = split_hi2(v.x, v.y, l0);
    __nv_bfloat162 h1 = split_hi2(v.z, v.w, l1);
    reinterpret_cast<__nv_bfloat162*>(hi)[2 * i]     = h0;
    reinterpret_cast<__nv_bfloat162*>(hi)[2 * i + 1] = h1;
    reinterpret_cast<__nv_bfloat162*>(lo)[2 * i]     = l0;
    reinterpret_cast<__nv_bfloat162*>(lo)[2 * i + 1] = l1;
}

__global__ void splitT4(const float* __restrict__ W0, const float* __restrict__ W1,
                        const float* __restrict__ W2, const float* __restrict__ W3,
                        __nv_bfloat16* __restrict__ hiT,
                        __nv_bfloat16* __restrict__ loT) {
    __shared__ float t[32][33];
    int z = blockIdx.z;
    const float* W = (z == 0) ? W0 : (z == 1) ? W1 : (z == 2) ? W2 : W3;
    size_t zoff = (size_t)z * DIM * DIM;
    int n0 = blockIdx.x * 32, k0 = blockIdx.y * 32;
    int tx = threadIdx.x, ty = threadIdx.y;           // (32, 8)
    #pragma unroll
    for (int i = 0; i < 4; ++i)
        t[ty * 4 + i][tx] = W[(size_t)(k0 + ty * 4 + i) * DIM + n0 + tx];
    __syncthreads();
    #pragma unroll
    for (int i = 0; i < 4; ++i) {
        int n = n0 + ty * 4 + i, k = k0 + tx;
        float a = t[tx][ty * 4 + i];
        __nv_bfloat16 h = __float2bfloat16(a);
        hiT[zoff + (size_t)n * DIM + k] = h;
        loT[zoff + (size_t)n * DIM + k] = __float2bfloat16(a - __bfloat162float(h));
    }
}

// ---------------------------------------------------------------------------
// GEMM tiles: 128x128, K-slab 64, 2-stage. Row stride 72 halves (144 B).
// 8 warps (2x4), warp tile 64x32. 12 slabs, 4 K-steps each.
// ---------------------------------------------------------------------------
#define TILE_B2  18432                 // 128 rows * 144 B
#define STAGE_B2 (4 * TILE_B2)         // Ah, Al, Bh, Bl = 73728
#define GSMEM2   (2 * STAGE_B2)        // 147456

__global__ __launch_bounds__(256, 1)
void gemm_qkv(const float* __restrict__ bq, const float* __restrict__ bk,
              const float* __restrict__ bv) {
    extern __shared__ char sm[];
    const int tid = threadIdx.x;
    const int lane = tid & 31;
    const int warp = tid >> 5;
    const int wm = warp >> 2, wn = warp & 3;
    const size_t row0 = (size_t)blockIdx.y * 128;
    const int bx = blockIdx.x;
    const int sel = bx / 6;
    const size_t col0g = (size_t)bx * 128;
    const int col0l = (bx - sel * 6) * 128;
    const uint32_t smb = smem_u32(sm);
    const float* bias = (sel == 0) ? bq : (sel == 1) ? bk : bv;

    float acc[4][4][4];
    #pragma unroll
    for (int i = 0; i < 4; ++i)
        #pragma unroll
        for (int j = 0; j < 4; ++j)
            #pragma unroll
            for (int q = 0; q < 4; ++q) acc[i][j][q] = 0.f;

    auto issue = [&](int s, int st) {
        const int k0 = s * 64;
        const uint32_t sb = smb + st * STAGE_B2;
        #pragma unroll
        for (int p = 0; p < 4; ++p) {
            int idx = tid + p * 256;           // 0..1023
            int r = idx >> 3, j = idx & 7;
            uint32_t d = sb + r * 144 + j * 16;
            CP_ASYNC16(d,             g_Xh + (row0 + r) * DIM + k0 + j * 8);
            CP_ASYNC16(d + TILE_B2,   g_Xl + (row0 + r) * DIM + k0 + j * 8);
            CP_ASYNC16(d + 2*TILE_B2, g_WTh + (col0g + r) * DIM + k0 + j * 8);
            CP_ASYNC16(d + 3*TILE_B2, g_WTl + (col0g + r) * DIM + k0 + j * 8);
        }
        CP_COMMIT();
    };

    const int a_row_l = (lane & 15);
    const int a_col_l = (lane >> 4) << 3;
    const int b_row_l = (lane & 7) + ((lane >> 4) << 3);
    const int b_col_l = ((lane >> 3) & 1) << 3;

    issue(0, 0); issue(1, 1);
    for (int s = 0; s < 12; ++s) {
        if (s < 11) CP_WAIT1(); else CP_WAIT0();
        __syncthreads();
        const uint32_t sb = smb + (s & 1) * STAGE_B2;
        const uint32_t tAh = sb, tAl = sb + TILE_B2;
        const uint32_t tBh = sb + 2 * TILE_B2, tBl = sb + 3 * TILE_B2;
        #pragma unroll
        for (int ks = 0; ks < 4; ++ks) {
            uint32_t ah[4][4], al[4][4], bh[4][2], bl[4][2];
            #pragma unroll
            for (int mi = 0; mi < 4; ++mi) {
                uint32_t off = (uint32_t)((wm * 64 + mi * 16 + a_row_l) * 144 +
                                          (ks * 16 + a_col_l) * 2);
                LDSM_X4(ah[mi][0], ah[mi][1], ah[mi][2], ah[mi][3], tAh + off);
                LDSM_X4(al[mi][0], al[mi][1], al[mi][2], al[mi][3], tAl + off);
            }
            #pragma unroll
            for (int nj = 0; nj < 2; ++nj) {
                uint32_t off = (uint32_t)((wn * 32 + nj * 16 + b_row_l) * 144 +
                                          (ks * 16 + b_col_l) * 2);
                uint32_t t0, t1, t2, t3;
                LDSM_X4(t0, t1, t2, t3, tBh + off);
                bh[nj * 2][0] = t0; bh[nj * 2][1] = t1;
                bh[nj * 2 + 1][0] = t2; bh[nj * 2 + 1][1] = t3;
                LDSM_X4(t0, t1, t2, t3, tBl + off);
                bl[nj * 2][0] = t0; bl[nj * 2][1] = t1;
                bl[nj * 2 + 1][0] = t2; bl[nj * 2 + 1][1] = t3;
            }
            #pragma unroll
            for (int mi = 0; mi < 4; ++mi)
                #pragma unroll
                for (int ni = 0; ni < 4; ++ni) {
                    MMA16816(acc[mi][ni], ah[mi], bh[ni]);
                    MMA16816(acc[mi][ni], al[mi], bh[ni]);
                    MMA16816(acc[mi][ni], ah[mi], bl[ni]);
                }
        }
        __syncthreads();
        if (s + 2 < 12) issue(s + 2, s & 1);
    }

    __nv_bfloat16* Ch = (sel == 0) ? g_Qh : g_Kh;
    __nv_bfloat16* Cl = (sel == 0) ? g_Ql : g_Kl;
    const int mbase = (int)row0 + wm * 64;
    const int nbase = col0l + wn * 32;
    #pragma unroll
    for (int mi = 0; mi < 4; ++mi) {
        #pragma unroll
        for (int ni = 0; ni < 4; ++ni) {
            int r = mbase + mi * 16 + (lane >> 2);
            int c = nbase + ni * 8 + (lane & 3) * 2;
            float b0 = bias[c], b1 = bias[c + 1];
            float v00 = acc[mi][ni][0] + b0, v01 = acc[mi][ni][1] + b1;
            float v10 = acc[mi][ni][2] + b0, v11 = acc[mi][ni][3] + b1;
            if (sel < 2) {
                __nv_bfloat162 lo0, lo1;
                __nv_bfloat162 hi0 = split_hi2(v00, v01, lo0);
                __nv_bfloat162 hi1 = split_hi2(v10, v11, lo1);
                *(__nv_bfloat162*)&Ch[(size_t)r * DIM + c] = hi0;
                *(__nv_bfloat162*)&Cl[(size_t)r * DIM + c] = lo0;
                *(__nv_bfloat162*)&Ch[(size_t)(r + 8) * DIM + c] = hi1;
                *(__nv_bfloat162*)&Cl[(size_t)(r + 8) * DIM + c] = lo1;
            } else {
                int b = r >> 10, n = r & 1023;
                size_t row_c0 = ((size_t)b * NHEAD + (c >> 6)) * HDIM + (c & 63);
                size_t row_c1 = ((size_t)b * NHEAD + ((c + 1) >> 6)) * HDIM + ((c + 1) & 63);
                __nv_bfloat16 h, l;
                h = __float2bfloat16(v00); l = __float2bfloat16(v00 - __bfloat162float(h));
                g_VTh[row_c0 * SEQ + n] = h; g_VTl[row_c0 * SEQ + n] = l;
                h = __float2bfloat16(v01); l = __float2bfloat16(v01 - __bfloat162float(h));
                g_VTh[row_c1 * SEQ + n] = h; g_VTl[row_c1 * SEQ + n] = l;
                h = __float2bfloat16(v10); l = __float2bfloat16(v10 - __bfloat162float(h));
                g_VTh[row_c0 * SEQ + n + 8] = h; g_VTl[row_c0 * SEQ + n + 8] = l;
                h = __float2bfloat16(v11); l = __float2bfloat16(v11 - __bfloat162float(h));
                g_VTh[row_c1 * SEQ + n + 8] = h; g_VTl[row_c1 * SEQ + n + 8] = l;
            }
        }
    }
}

__global__ __launch_bounds__(256, 1)
void gemm_oproj(const __nv_bfloat16* __restrict__ Ah,
                const __nv_bfloat16* __restrict__ Al,
                const __nv_bfloat16* __restrict__ Bh,
                const __nv_bfloat16* __restrict__ Bl,
                const float* __restrict__ bias, float* __restrict__ Cf) {
    extern __shared__ char sm[];
    const int tid = threadIdx.x;
    const int lane = tid & 31;
    const int warp = tid >> 5;
    const int wm = warp >> 2, wn = warp & 3;
    const size_t row0 = (size_t)blockIdx.y * 128;
    const size_t col0 = (size_t)blockIdx.x * 128;
    const uint32_t smb = smem_u32(sm);

    float acc[4][4][4];
    #pragma unroll
    for (int i = 0; i < 4; ++i)
        #pragma unroll
        for (int j = 0; j < 4; ++j)
            #pragma unroll
            for (int q = 0; q < 4; ++q) acc[i][j][q] = 0.f;

    auto issue = [&](int s, int st) {
        const int k0 = s * 64;
        const uint32_t sb = smb + st * STAGE_B2;
        #pragma unroll
        for (int p = 0; p < 4; ++p) {
            int idx = tid + p * 256;
            int r = idx >> 3, j = idx & 7;
            uint32_t d = sb + r * 144 + j * 16;
            CP_ASYNC16(d,             Ah + (row0 + r) * DIM + k0 + j * 8);
            CP_ASYNC16(d + TILE_B2,   Al + (row0 + r) * DIM + k0 + j * 8);
            CP_ASYNC16(d + 2*TILE_B2, Bh + (col0 + r) * DIM + k0 + j * 8);
            CP_ASYNC16(d + 3*TILE_B2, Bl + (col0 + r) * DIM + k0 + j * 8);
        }
        CP_COMMIT();
    };

    const int a_row_l = (lane & 15);
    const int a_col_l = (lane >> 4) << 3;
    const int b_row_l = (lane & 7) + ((lane >> 4) << 3);
    const int b_col_l = ((lane >> 3) & 1) << 3;

    issue(0, 0); issue(1, 1);
    for (int s = 0; s < 12; ++s) {
        if (s < 11) CP_WAIT1(); else CP_WAIT0();
        __syncthreads();
        const uint32_t sb = smb + (s & 1) * STAGE_B2;
        const uint32_t tAh = sb, tAl = sb + TILE_B2;
        const uint32_t tBh = sb + 2 * TILE_B2, tBl = sb + 3 * TILE_B2;
        #pragma unroll
        for (int ks = 0; ks < 4; ++ks) {
            uint32_t ah[4][4], al[4][4], bh[4][2], bl[4][2];
            #pragma unroll
            for (int mi = 0; mi < 4; ++mi) {
                uint32_t off = (uint32_t)((wm * 64 + mi * 16 + a_row_l) * 144 +
                                          (ks * 16 + a_col_l) * 2);
                LDSM_X4(ah[mi][0], ah[mi][1], ah[mi][2], ah[mi][3], tAh + off);
                LDSM_X4(al[mi][0], al[mi][1], al[mi][2], al[mi][3], tAl + off);
            }
            #pragma unroll
            for (int nj = 0; nj < 2; ++nj) {
                uint32_t off = (uint32_t)((wn * 32 + nj * 16 + b_row_l) * 144 +
                                          (ks * 16 + b_col_l) * 2);
                uint32_t t0, t1, t2, t3;
                LDSM_X4(t0, t1, t2, t3, tBh + off);
                bh[nj * 2][0] = t0; bh[nj * 2][1] = t1;
                bh[nj * 2 + 1][0] = t2; bh[nj * 2 + 1][1] = t3;
                LDSM_X4(t0, t1, t2, t3, tBl + off);
                bl[nj * 2][0] = t0; bl[nj * 2][1] = t1;
                bl[nj * 2 + 1][0] = t2; bl[nj * 2 + 1][1] = t3;
            }
            #pragma unroll
            for (int mi = 0; mi < 4; ++mi)
                #pragma unroll
                for (int ni = 0; ni < 4; ++ni) {
                    MMA16816(acc[mi][ni], ah[mi], bh[ni]);
                    MMA16816(acc[mi][ni], al[mi], bh[ni]);
                    MMA16816(acc[mi][ni], ah[mi], bl[ni]);
                }
        }
        __syncthreads();
        if (s + 2 < 12) issue(s + 2, s & 1);
    }

    const int mbase = (int)row0 + wm * 64;
    const int nbase = (int)col0 + wn * 32;
    #pragma unroll
    for (int mi = 0; mi < 4; ++mi) {
        #pragma unroll
        for (int ni = 0; ni < 4; ++ni) {
            int r = mbase + mi * 16 + (lane >> 2);
            int c = nbase + ni * 8 + (lane & 3) * 2;
            float b0 = bias[c], b1 = bias[c + 1];
            *(float2*)&Cf[(size_t)r * DIM + c] =
                make_float2(acc[mi][ni][0] + b0, acc[mi][ni][1] + b1);
            *(float2*)&Cf[(size_t)(r + 8) * DIM + c] =
                make_float2(acc[mi][ni][2] + b0, acc[mi][ni][3] + b1);
        }
    }
}

// ---------------------------------------------------------------------------
// Fused scores + softmax: 32-row x 1024-col tile per block, 512 threads /
// 16 warps (2 row-groups x 8 column-owners). Proven R12 config.
// ---------------------------------------------------------------------------
#define AF_QSZ 4608                   // 32 rows * 144 B
#define AF_Q0  0
#define AF_Q1  AF_QSZ
#define AF_K0  (2 * AF_QSZ)           // 9216
#define AF_KSZ 18432                  // 128 rows * 144 B
#define AF_RED (AF_K0 + 4 * AF_KSZ)   // 82944
#define AF_SMEM (AF_RED + 2048)       // 84992

__global__ __launch_bounds__(512, 1)
void attn_fused(float* __restrict__ Wt) {
    extern __shared__ char sm[];
    const uint32_t smb = smem_u32(sm);
    float* red_max = (float*)(sm + AF_RED);          // [32][8]
    float* red_sum = (float*)(sm + AF_RED + 1024);   // [32][8]
    const int tid = threadIdx.x;
    const int lane = tid & 31;
    const int warp = tid >> 5;                       // 0..15
    const int wg = warp >> 3;                        // row group 0/1
    const int wn = warp & 7;                         // col owner 0..7
    const int bh = blockIdx.y;
    const int b = bh / NHEAD, h = bh - b * NHEAD;
    const size_t i0 = (size_t)blockIdx.x * 32;
    const __nv_bfloat16* Qh = g_Qh + ((size_t)b * SEQ) * DIM + h * HDIM;
    const __nv_bfloat16* Ql = g_Ql + ((size_t)b * SEQ) * DIM + h * HDIM;
    const __nv_bfloat16* Kh = g_Kh + ((size_t)b * SEQ) * DIM + h * HDIM;
    const __nv_bfloat16* Kl = g_Kl + ((size_t)b * SEQ) * DIM + h * HDIM;

    float acc[8][2][4];
    #pragma unroll
    for (int c = 0; c < 8; ++c)
        #pragma unroll
        for (int j = 0; j < 2; ++j)
            #pragma unroll
            for (int q = 0; q < 4; ++q) acc[c][j][q] = 0.f;

    {
        int t = tid & 255;
        int r = t >> 3, j = t & 7;
        uint32_t d = smb + ((tid < 256) ? AF_Q0 : AF_Q1) + r * 144 + j * 16;
        const __nv_bfloat16* src = (tid < 256) ? Qh : Ql;
        CP_ASYNC16(d, src + (i0 + r) * DIM + j * 8);
        #pragma unroll
        for (int p = 0; p < 2; ++p) {
            int idx = tid + p * 512;
            int kr = idx >> 3, kj = idx & 7;
            uint32_t kd = smb + AF_K0 + kr * 144 + kj * 16;
            CP_ASYNC16(kd,          Kh + (size_t)kr * DIM + kj * 8);
            CP_ASYNC16(kd + AF_KSZ, Kl + (size_t)kr * DIM + kj * 8);
        }
        CP_COMMIT();
        #pragma unroll
        for (int p = 0; p < 2; ++p) {
            int idx = tid + p * 512;
            int kr = idx >> 3, kj = idx & 7;
            uint32_t kd = smb + AF_K0 + 2 * AF_KSZ + kr * 144 + kj * 16;
            CP_ASYNC16(kd,          Kh + (size_t)(128 + kr) * DIM + kj * 8);
            CP_ASYNC16(kd + AF_KSZ, Kl + (size_t)(128 + kr) * DIM + kj * 8);
        }
        CP_COMMIT();
    }

    const int a_row_l = (lane & 15);
    const int a_col_l = (lane >> 4) << 3;
    const int b_row_l = (lane & 7) + ((lane >> 4) << 3);
    const int b_col_l = ((lane >> 3) & 1) << 3;

    uint32_t qh[4][4], ql[4][4];
    bool qloaded = false;

    for (int c = 0; c < 8; ++c) {
        if (c < 7) CP_WAIT1(); else CP_WAIT0();
        __syncthreads();
        if (!qloaded) {
            #pragma unroll
            for (int ks = 0; ks < 4; ++ks) {
                uint32_t off = (uint32_t)((wg * 16 + a_row_l) * 144 +
                                          (ks * 16 + a_col_l) * 2);
                LDSM_X4(qh[ks][0], qh[ks][1], qh[ks][2], qh[ks][3],
                        smb + AF_Q0 + off);
                LDSM_X4(ql[ks][0], ql[ks][1], ql[ks][2], ql[ks][3],
                        smb + AF_Q1 + off);
            }
            qloaded = true;
        }
        const uint32_t kb = smb + AF_K0 + (c & 1) * 2 * AF_KSZ;
        #pragma unroll
        for (int ks = 0; ks < 4; ++ks) {
            uint32_t bh2[2][2], bl2[2][2];
            {
                uint32_t off = (uint32_t)((wn * 16 + b_row_l) * 144 +
                                          (ks * 16 + b_col_l) * 2);
                uint32_t t0, t1, t2, t3;
                LDSM_X4(t0, t1, t2, t3, kb + off);
                bh2[0][0] = t0; bh2[0][1] = t1;
                bh2[1][0] = t2; bh2[1][1] = t3;
                LDSM_X4(t0, t1, t2, t3, kb + AF_KSZ + off);
                bl2[0][0] = t0; bl2[0][1] = t1;
                bl2[1][0] = t2; bl2[1][1] = t3;
            }
            #pragma unroll
            for (int ni = 0; ni < 2; ++ni) {
                MMA16816(acc[c][ni], qh[ks], bh2[ni]);
                MMA16816(acc[c][ni], ql[ks], bh2[ni]);
                MMA16816(acc[c][ni], qh[ks], bl2[ni]);
            }
        }
        __syncthreads();
        if (c + 2 < 8) {
            const uint32_t kd0 = smb + AF_K0 + (c & 1) * 2 * AF_KSZ;
            const size_t j0n = (size_t)(c + 2) * 128;
            #pragma unroll
            for (int p = 0; p < 2; ++p) {
                int idx = tid + p * 512;
                int kr = idx >> 3, kj = idx & 7;
                uint32_t kd = kd0 + kr * 144 + kj * 16;
                CP_ASYNC16(kd,          Kh + (j0n + kr) * DIM + kj * 8);
                CP_ASYNC16(kd + AF_KSZ, Kl + (j0n + kr) * DIM + kj * 8);
            }
            CP_COMMIT();
        }
    }

    #pragma unroll
    for (int c = 0; c < 8; ++c)
        #pragma unroll
        for (int j = 0; j < 2; ++j)
            #pragma unroll
            for (int q = 0; q < 4; ++q) acc[c][j][q] *= 0.125f;

    const int R0 = wg * 16 + (lane >> 2);
    const int R1 = R0 + 8;

    float m0 = -1e30f, m1 = -1e30f;
    #pragma unroll
    for (int c = 0; c < 8; ++c)
        #pragma unroll
        for (int j = 0; j < 2; ++j) {
            m0 = fmaxf(m0, fmaxf(acc[c][j][0], acc[c][j][1]));
            m1 = fmaxf(m1, fmaxf(acc[c][j][2], acc[c][j][3]));
        }
    m0 = fmaxf(m0, __shfl_xor_sync(~0u, m0, 1));
    m0 = fmaxf(m0, __shfl_xor_sync(~0u, m0, 2));
    m1 = fmaxf(m1, __shfl_xor_sync(~0u, m1, 1));
    m1 = fmaxf(m1, __shfl_xor_sync(~0u, m1, 2));
    if ((lane & 3) == 0) {
        red_max[R0 * 8 + wn] = m0;
        red_max[R1 * 8 + wn] = m1;
    }
    __syncthreads();
    m0 = red_max[R0 * 8];
    m1 = red_max[R1 * 8];
    #pragma unroll
    for (int i = 1; i < 8; ++i) {
        m0 = fmaxf(m0, red_max[R0 * 8 + i]);
        m1 = fmaxf(m1, red_max[R1 * 8 + i]);
    }

    float s0 = 0.f, s1 = 0.f;
    #pragma unroll
    for (int c = 0; c < 8; ++c)
        #pragma unroll
        for (int j = 0; j < 2; ++j) {
            acc[c][j][0] = __expf(acc[c][j][0] - m0);
            acc[c][j][1] = __expf(acc[c][j][1] - m0);
            acc[c][j][2] = __expf(acc[c][j][2] - m1);
            acc[c][j][3] = __expf(acc[c][j][3] - m1);
            s0 += acc[c][j][0] + acc[c][j][1];
            s1 += acc[c][j][2] + acc[c][j][3];
        }
    s0 += __shfl_xor_sync(~0u, s0, 1);
    s0 += __shfl_xor_sync(~0u, s0, 2);
    s1 += __shfl_xor_sync(~0u, s1, 1);
    s1 += __shfl_xor_sync(~0u, s1, 2);
    if ((lane & 3) == 0) {
        red_sum[R0 * 8 + wn] = s0;
        red_sum[R1 * 8 + wn] = s1;
    }
    __syncthreads();
    s0 = 0.f; s1 = 0.f;
    #pragma unroll
    for (int i = 0; i < 8; ++i) {
        s0 += red_sum[R0 * 8 + i];
        s1 += red_sum[R1 * 8 + i];
    }
    float inv0 = 1.0f / s0, inv1 = 1.0f / s1;

    float* Wb = Wt + ((size_t)bh * SEQ + i0) * SEQ;
    #pragma unroll
    for (int c = 0; c < 8; ++c)
        #pragma unroll
        for (int j = 0; j < 2; ++j) {
            int col = c * 128 + wn * 16 + j * 8 + (lane & 3) * 2;
            *(float2*)&Wb[(size_t)R0 * SEQ + col] =
                make_float2(acc[c][j][0] * inv0, acc[c][j][1] * inv0);
            *(float2*)&Wb[(size_t)R1 * SEQ + col] =
                make_float2(acc[c][j][2] * inv1, acc[c][j][3] * inv1);
        }
}

// ---------------------------------------------------------------------------
// O = P @ V (256x64 tile, proven config). fp32 P in-kernel split; VT cp.async.
// ---------------------------------------------------------------------------
#define AV_ATILE 20480
#define AV_BTILE 5120
#define AV_ASTG  (2 * AV_ATILE)
#define AV_BSTG  (2 * AV_BTILE)
#define AV_B0    (2 * AV_ASTG)
#define AV_SMEM  (2 * AV_ASTG + 2 * AV_BSTG)

__global__ __launch_bounds__(256, 1)
void av_mma(const float* __restrict__ Wt) {
    extern __shared__ char sm[];
    const int tid = threadIdx.x;
    const int lane = tid & 31;
    const int warp = tid >> 5;
    const int wm = warp >> 1, wn = warp & 1;
    const int bh = blockIdx.z;
    const int b = bh / NHEAD, h = bh - b * NHEAD;
    const size_t m0 = (size_t)blockIdx.y * 256;
    const uint32_t smb = smem_u32(sm);
    const float* P = Wt + ((size_t)bh * SEQ + m0) * SEQ;
    const __nv_bfloat16* Bh = g_VTh + (size_t)bh * HDIM * SEQ;
    const __nv_bfloat16* Bl = g_VTl + (size_t)bh * HDIM * SEQ;

    float acc[4][4][4];
    #pragma unroll
    for (int i = 0; i < 4; ++i)
        #pragma unroll
        for (int j = 0; j < 4; ++j)
            #pragma unroll
            for (int q = 0; q < 4; ++q) acc[i][j][q] = 0.f;

    const int ar = tid >> 3, aj = tid & 7;

    auto issueB = [&](int s, int st) {
        const int k0 = s * 32;
        int r = tid >> 2, j = tid & 3;
        if (r < 64) {
            uint32_t d = smb + AV_B0 + st * AV_BSTG + r * 80 + j * 16;
            CP_ASYNC16(d,            Bh + (size_t)r * SEQ + k0 + j * 8);
            CP_ASYNC16(d + AV_BTILE, Bl + (size_t)r * SEQ + k0 + j * 8);
        }
        CP_COMMIT();
    };

    float4 areg[8];
    auto ldgA = [&](int s) {
        const int k0 = s * 32;
        #pragma unroll
        for (int g = 0; g < 8; ++g)
            areg[g] = *(const float4*)&P[(size_t)(ar + 32 * g) * SEQ + k0 + aj * 4];
    };

    const int a_row_l = (lane & 15);
    const int a_col_l = (lane >> 4) << 3;
    const int b_row_l = (lane & 7) + ((lane >> 4) << 3);
    const int b_col_l = ((lane >> 3) & 1) << 3;

    issueB(0, 0);
    issueB(1, 1);
    ldgA(0);
    for (int s = 0; s < 32; ++s) {
        {
            const uint32_t ab = smb + (s & 1) * AV_ASTG;
            #pragma unroll
            for (int g = 0; g < 8; ++g) {
                float4 v = areg[g];
                __nv_bfloat162 lo0, lo1;
                __nv_bfloat162 hi0 = split_hi2(v.x, v.y, lo0);
                __nv_bfloat162 hi1 = split_hi2(v.z, v.w, lo1);
                uint32_t off = (ab - smb) + (ar + 32 * g) * 80 + aj * 8;
                *(__nv_bfloat162*)(sm + off)                = hi0;
                *(__nv_bfloat162*)(sm + off + 4)            = hi1;
                *(__nv_bfloat162*)(sm + off + AV_ATILE)     = lo0;
                *(__nv_bfloat162*)(sm + off + AV_ATILE + 4) = lo1;
            }
        }
        if (s < 31) CP_WAIT1(); else CP_WAIT0();
        __syncthreads();
        if (s + 1 < 32) ldgA(s + 1);

        const uint32_t ab = smb + (s & 1) * AV_ASTG;
        const uint32_t tAh = ab, tAl = ab + AV_ATILE;
        const uint32_t bb = smb + AV_B0 + (s & 1) * AV_BSTG;
        const uint32_t tBh = bb, tBl = bb + AV_BTILE;
        #pragma unroll
        for (int ks = 0; ks < 2; ++ks) {
            uint32_t ah[4][4], al[4][4], bh2[4][2], bl2[4][2];
            #pragma unroll
            for (int mi = 0; mi < 4; ++mi) {
                uint32_t off = (uint32_t)((wm * 64 + mi * 16 + a_row_l) * 80 +
                                          (ks * 16 + a_col_l) * 2);
                LDSM_X4(ah[mi][0], ah[mi][1], ah[mi][2], ah[mi][3], tAh + off);
                LDSM_X4(al[mi][0], al[mi][1], al[mi][2], al[mi][3], tAl + off);
            }
            #pragma unroll
            for (int nj = 0; nj < 2; ++nj) {
                uint32_t off = (uint32_t)((wn * 32 + nj * 16 + b_row_l) * 80 +
                                          (ks * 16 + b_col_l) * 2);
                uint32_t t0, t1, t2, t3;
                LDSM_X4(t0, t1, t2, t3, tBh + off);
                bh2[nj * 2][0] = t0; bh2[nj * 2][1] = t1;
                bh2[nj * 2 + 1][0] = t2; bh2[nj * 2 + 1][1] = t3;
                LDSM_X4(t0, t1, t2, t3, tBl + off);
                bl2[nj * 2][0] = t0; bl2[nj * 2][1] = t1;
                bl2[nj * 2 + 1][0] = t2; bl2[nj * 2 + 1][1] = t3;
            }
            #pragma unroll
            for (int mi = 0; mi < 4; ++mi)
                #pragma unroll
                for (int ni = 0; ni < 4; ++ni) {
                    MMA16816(acc[mi][ni], ah[mi], bh2[ni]);
                    MMA16816(acc[mi][ni], al[mi], bh2[ni]);
                    MMA16816(acc[mi][ni], ah[mi], bl2[ni]);
                }
        }
        __syncthreads();
        if (s + 2 < 32) issueB(s + 2, (s) & 1);
    }

    #pragma unroll
    for (int mi = 0; mi < 4; ++mi) {
        #pragma unroll
        for (int ni = 0; ni < 4; ++ni) {
            int rl = wm * 64 + mi * 16 + (lane >> 2);
            int cl = wn * 32 + ni * 8 + (lane & 3) * 2;
            size_t r = (size_t)b * SEQ + m0 + rl;
            size_t c = h * HDIM + cl;
            __nv_bfloat162 lo0, lo1;
            __nv_bfloat162 hi0 = split_hi2(acc[mi][ni][0], acc[mi][ni][1], lo0);
            __nv_bfloat162 hi1 = split_hi2(acc[mi][ni][2], acc[mi][ni][3], lo1);
            *(__nv_bfloat162*)&g_Oh[r * DIM + c] = hi0;
            *(__nv_bfloat162*)&g_Ol[r * DIM + c] = lo0;
            *(__nv_bfloat162*)&g_Oh[(r + 8) * DIM + c] = hi1;
            *(__nv_bfloat162*)&g_Ol[(r + 8) * DIM + c] = lo1;
        }
    }
}

// ---------------------------------------------------------------------------
extern "C" void kernel_launch(void* const* d_in, const int* in_sizes, int n_in,
                              void* d_out, int out_size) {
    const float* x  = (const float*)d_in[0];
    const float* Wq = (const float*)d_in[1];
    const float* bq = (const float*)d_in[2];
    const float* Wk = (const float*)d_in[3];
    const float* bk = (const float*)d_in[4];
    const float* Wv = (const float*)d_in[5];
    const float* bv = (const float*)d_in[6];
    const float* Wo = (const float*)d_in[7];
    const float* bo = (const float*)d_in[8];

    float* out = (float*)d_out;
    float* wts = out + OUT_OFF;

    cudaFuncSetAttribute(gemm_qkv,
                         cudaFuncAttributeMaxDynamicSharedMemorySize, GSMEM2);
    cudaFuncSetAttribute(gemm_oproj,
                         cudaFuncAttributeMaxDynamicSharedMemorySize, GSMEM2);
    cudaFuncSetAttribute(attn_fused,
                         cudaFuncAttributeMaxDynamicSharedMemorySize, AF_SMEM);
    cudaFuncSetAttribute(av_mma,
                         cudaFuncAttributeMaxDynamicSharedMemorySize, AV_SMEM);

    __nv_bfloat16 *Xh, *Xl, *Oh, *Ol, *WTh, *WTl;
    cudaGetSymbolAddress((void**)&Xh, g_Xh);
    cudaGetSymbolAddress((void**)&Xl, g_Xl);
    cudaGetSymbolAddress((void**)&Oh, g_Oh);
    cudaGetSymbolAddress((void**)&Ol, g_Ol);
    cudaGetSymbolAddress((void**)&WTh, g_WTh);
    cudaGetSymbolAddress((void**)&WTl, g_WTl);

    const int NELEM = MROWS * DIM;
    split_kernel<<<NELEM / 4 / 256, 256>>>(x, Xh, Xl, NELEM / 4);
    splitT4<<<dim3(DIM / 32, DIM / 32, 4), dim3(32, 8)>>>(Wq, Wk, Wv, Wo,
                                                          WTh, WTl);

    gemm_qkv<<<dim3(18, MROWS / 128), 256, GSMEM2>>>(bq, bk, bv);

    attn_fused<<<dim3(SEQ / 32, BH), 512, AF_SMEM>>>(wts);
    av_mma<<<dim3(1, SEQ / 256, BH), 256, AV_SMEM>>>(wts);

    gemm_oproj<<<dim3(DIM / 128, MROWS / 128), 256, GSMEM2>>>(
        Oh, Ol, WTh + 3 * DIM * DIM, WTl + 3 * DIM * DIM, bo, out);
}

// round 15
// speedup vs baseline: 1.1537x; 1.0217x over previous
#include <cuda_runtime.h>
#include <cuda_bf16.h>
#include <cstdint>

#define BATCH 8
#define SEQ   1024
#define DIM   768
#define NHEAD 12
#define HDIM  64
#define BH    (BATCH * NHEAD)     // 96
#define MROWS (BATCH * SEQ)       // 8192
#define OUT_OFF ((size_t)MROWS * DIM)

// ---------------- scratch (__device__ globals; no allocs allowed) ----------
__device__ __nv_bfloat16 g_Xh[MROWS * DIM];
__device__ __nv_bfloat16 g_Xl[MROWS * DIM];
__device__ __nv_bfloat16 g_Qh[MROWS * DIM];
__device__ __nv_bfloat16 g_Ql[MROWS * DIM];
__device__ __nv_bfloat16 g_Kh[MROWS * DIM];
__device__ __nv_bfloat16 g_Kl[MROWS * DIM];
__device__ __nv_bfloat16 g_VTh[BH * HDIM * SEQ];  // [bh*64+d][n]
__device__ __nv_bfloat16 g_VTl[BH * HDIM * SEQ];
__device__ __nv_bfloat16 g_Oh[MROWS * DIM];
__device__ __nv_bfloat16 g_Ol[MROWS * DIM];
__device__ __nv_bfloat16 g_WTh[4 * DIM * DIM];    // W^T hi: [q;k;v;o] rows
__device__ __nv_bfloat16 g_WTl[4 * DIM * DIM];

// ---------------- helpers --------------------------------------------------
__device__ __forceinline__ uint32_t smem_u32(const void* p) {
    uint32_t a;
    asm("{ .reg .u64 t; cvta.to.shared.u64 t, %1; cvt.u32.u64 %0, t; }"
        : "=r"(a) : "l"(p));
    return a;
}
#define CP_ASYNC16(sm, gp) \
    asm volatile("cp.async.cg.shared.global [%0], [%1], 16;" \
                 :: "r"(sm), "l"(gp) : "memory")
#define CP_COMMIT() asm volatile("cp.async.commit_group;" ::: "memory")
#define CP_WAIT1()  asm volatile("cp.async.wait_group 1;" ::: "memory")
#define CP_WAIT0()  asm volatile("cp.async.wait_group 0;" ::: "memory")
#define LDSM_X4(r0, r1, r2, r3, addr) \
    asm volatile("ldmatrix.sync.aligned.m8n8.x4.shared.b16 {%0,%1,%2,%3}, [%4];" \
                 : "=r"(r0), "=r"(r1), "=r"(r2), "=r"(r3) : "r"(addr))
#define MMA16816(d, a, b) \
    asm volatile("mma.sync.aligned.m16n8k16.row.col.f32.bf16.bf16.f32 " \
                 "{%0,%1,%2,%3}, {%4,%5,%6,%7}, {%8,%9}, {%0,%1,%2,%3};" \
                 : "+f"((d)[0]), "+f"((d)[1]), "+f"((d)[2]), "+f"((d)[3]) \
                 : "r"((a)[0]), "r"((a)[1]), "r"((a)[2]), "r"((a)[3]), \
                   "r"((b)[0]), "r"((b)[1]))

__device__ __forceinline__ __nv_bfloat162 split_hi2(float a, float b,
                                                    __nv_bfloat162& lo) {
    __nv_bfloat16 h0 = __float2bfloat16(a);
    __nv_bfloat16 h1 = __float2bfloat16(b);
    lo.x = __float2bfloat16(a - __bfloat162float(h0));
    lo.y = __float2bfloat16(b - __bfloat162float(h1));
    __nv_bfloat162 hi; hi.x = h0; hi.y = h1;
    return hi;
}

// ---------------------------------------------------------------------------
__global__ void split_kernel(const float* __restrict__ src,
                             __nv_bfloat16* __restrict__ hi,
                             __nv_bfloat16* __restrict__ lo, int n4) {
    int i = blockIdx.x * blockDim.x + threadIdx.x;
    if (i >= n4) return;
    float4 v = reinterpret_cast<const float4*>(src)[i];
    __nv_bfloat162 l0, l1;
    __nv_bfloat162 h0 = split_hi2(v.x, v.y, l0);
    __nv_bfloat162 h1 = split_hi2(v.z, v.w, l1);
    reinterpret_cast<__nv_bfloat162*>(hi)[2 * i]     = h0;
    reinterpret_cast<__nv_bfloat162*>(hi)[2 * i + 1] = h1;
    reinterpret_cast<__nv_bfloat162*>(lo)[2 * i]     = l0;
    reinterpret_cast<__nv_bfloat162*>(lo)[2 * i + 1] = l1;
}

__global__ void splitT4(const float* __restrict__ W0, const float* __restrict__ W1,
                        const float* __restrict__ W2, const float* __restrict__ W3,
                        __nv_bfloat16* __restrict__ hiT,
                        __nv_bfloat16* __restrict__ loT) {
    __shared__ float t[32][33];
    int z = blockIdx.z;
    const float* W = (z == 0) ? W0 : (z == 1) ? W1 : (z == 2) ? W2 : W3;
    size_t zoff = (size_t)z * DIM * DIM;
    int n0 = blockIdx.x * 32, k0 = blockIdx.y * 32;
    int tx = threadIdx.x, ty = threadIdx.y;           // (32, 8)
    #pragma unroll
    for (int i = 0; i < 4; ++i)
        t[ty * 4 + i][tx] = W[(size_t)(k0 + ty * 4 + i) * DIM + n0 + tx];
    __syncthreads();
    #pragma unroll
    for (int i = 0; i < 4; ++i) {
        int n = n0 + ty * 4 + i, k = k0 + tx;
        float a = t[tx][ty * 4 + i];
        __nv_bfloat16 h = __float2bfloat16(a);
        hiT[zoff + (size_t)n * DIM + k] = h;
        loT[zoff + (size_t)n * DIM + k] = __float2bfloat16(a - __bfloat162float(h));
    }
}

// ---------------------------------------------------------------------------
// GEMM tiles: 128x128, K-slab 64, 3-stage, single-sync mainloop.
// Row stride 72 halves (144 B). 8 warps (2x4), warp tile 64x32. 12 slabs.
// ---------------------------------------------------------------------------
#define TILE_B2  18432                 // 128 rows * 144 B
#define STAGE_B2 (4 * TILE_B2)         // Ah, Al, Bh, Bl = 73728
#define GSMEM3S  (3 * STAGE_B2)        // 221184

__global__ __launch_bounds__(256, 1)
void gemm_qkv(const float* __restrict__ bq, const float* __restrict__ bk,
              const float* __restrict__ bv) {
    extern __shared__ char sm[];
    const int tid = threadIdx.x;
    const int lane = tid & 31;
    const int warp = tid >> 5;
    const int wm = warp >> 2, wn = warp & 3;
    const size_t row0 = (size_t)blockIdx.y * 128;
    const int bx = blockIdx.x;
    const int sel = bx / 6;
    const size_t col0g = (size_t)bx * 128;
    const int col0l = (bx - sel * 6) * 128;
    const uint32_t smb = smem_u32(sm);
    const float* bias = (sel == 0) ? bq : (sel == 1) ? bk : bv;

    float acc[4][4][4];
    #pragma unroll
    for (int i = 0; i < 4; ++i)
        #pragma unroll
        for (int j = 0; j < 4; ++j)
            #pragma unroll
            for (int q = 0; q < 4; ++q) acc[i][j][q] = 0.f;

    auto issue = [&](int s, int st) {
        const int k0 = s * 64;
        const uint32_t sb = smb + st * STAGE_B2;
        #pragma unroll
        for (int p = 0; p < 4; ++p) {
            int idx = tid + p * 256;           // 0..1023
            int r = idx >> 3, j = idx & 7;
            uint32_t d = sb + r * 144 + j * 16;
            CP_ASYNC16(d,             g_Xh + (row0 + r) * DIM + k0 + j * 8);
            CP_ASYNC16(d + TILE_B2,   g_Xl + (row0 + r) * DIM + k0 + j * 8);
            CP_ASYNC16(d + 2*TILE_B2, g_WTh + (col0g + r) * DIM + k0 + j * 8);
            CP_ASYNC16(d + 3*TILE_B2, g_WTl + (col0g + r) * DIM + k0 + j * 8);
        }
        CP_COMMIT();
    };

    const int a_row_l = (lane & 15);
    const int a_col_l = (lane >> 4) << 3;
    const int b_row_l = (lane & 7) + ((lane >> 4) << 3);
    const int b_col_l = ((lane >> 3) & 1) << 3;

    issue(0, 0); issue(1, 1);
    for (int s = 0; s < 12; ++s) {
        if (s < 11) CP_WAIT1(); else CP_WAIT0();
        __syncthreads();
        if (s + 2 < 12) issue(s + 2, (s + 2) % 3);
        const uint32_t sb = smb + (s % 3) * STAGE_B2;
        const uint32_t tAh = sb, tAl = sb + TILE_B2;
        const uint32_t tBh = sb + 2 * TILE_B2, tBl = sb + 3 * TILE_B2;
        #pragma unroll
        for (int ks = 0; ks < 4; ++ks) {
            uint32_t ah[4][4], al[4][4], bh[4][2], bl[4][2];
            #pragma unroll
            for (int mi = 0; mi < 4; ++mi) {
                uint32_t off = (uint32_t)((wm * 64 + mi * 16 + a_row_l) * 144 +
                                          (ks * 16 + a_col_l) * 2);
                LDSM_X4(ah[mi][0], ah[mi][1], ah[mi][2], ah[mi][3], tAh + off);
                LDSM_X4(al[mi][0], al[mi][1], al[mi][2], al[mi][3], tAl + off);
            }
            #pragma unroll
            for (int nj = 0; nj < 2; ++nj) {
                uint32_t off = (uint32_t)((wn * 32 + nj * 16 + b_row_l) * 144 +
                                          (ks * 16 + b_col_l) * 2);
                uint32_t t0, t1, t2, t3;
                LDSM_X4(t0, t1, t2, t3, tBh + off);
                bh[nj * 2][0] = t0; bh[nj * 2][1] = t1;
                bh[nj * 2 + 1][0] = t2; bh[nj * 2 + 1][1] = t3;
                LDSM_X4(t0, t1, t2, t3, tBl + off);
                bl[nj * 2][0] = t0; bl[nj * 2][1] = t1;
                bl[nj * 2 + 1][0] = t2; bl[nj * 2 + 1][1] = t3;
            }
            #pragma unroll
            for (int mi = 0; mi < 4; ++mi)
                #pragma unroll
                for (int ni = 0; ni < 4; ++ni) {
                    MMA16816(acc[mi][ni], ah[mi], bh[ni]);
                    MMA16816(acc[mi][ni], al[mi], bh[ni]);
                    MMA16816(acc[mi][ni], ah[mi], bl[ni]);
                }
        }
    }

    __nv_bfloat16* Ch = (sel == 0) ? g_Qh : g_Kh;
    __nv_bfloat16* Cl = (sel == 0) ? g_Ql : g_Kl;
    const int mbase = (int)row0 + wm * 64;
    const int nbase = col0l + wn * 32;
    #pragma unroll
    for (int mi = 0; mi < 4; ++mi) {
        #pragma unroll
        for (int ni = 0; ni < 4; ++ni) {
            int r = mbase + mi * 16 + (lane >> 2);
            int c = nbase + ni * 8 + (lane & 3) * 2;
            float b0 = bias[c], b1 = bias[c + 1];
            float v00 = acc[mi][ni][0] + b0, v01 = acc[mi][ni][1] + b1;
            float v10 = acc[mi][ni][2] + b0, v11 = acc[mi][ni][3] + b1;
            if (sel < 2) {
                __nv_bfloat162 lo0, lo1;
                __nv_bfloat162 hi0 = split_hi2(v00, v01, lo0);
                __nv_bfloat162 hi1 = split_hi2(v10, v11, lo1);
                *(__nv_bfloat162*)&Ch[(size_t)r * DIM + c] = hi0;
                *(__nv_bfloat162*)&Cl[(size_t)r * DIM + c] = lo0;
                *(__nv_bfloat162*)&Ch[(size_t)(r + 8) * DIM + c] = hi1;
                *(__nv_bfloat162*)&Cl[(size_t)(r + 8) * DIM + c] = lo1;
            } else {
                int b = r >> 10, n = r & 1023;
                size_t row_c0 = ((size_t)b * NHEAD + (c >> 6)) * HDIM + (c & 63);
                size_t row_c1 = ((size_t)b * NHEAD + ((c + 1) >> 6)) * HDIM + ((c + 1) & 63);
                __nv_bfloat16 h, l;
                h = __float2bfloat16(v00); l = __float2bfloat16(v00 - __bfloat162float(h));
                g_VTh[row_c0 * SEQ + n] = h; g_VTl[row_c0 * SEQ + n] = l;
                h = __float2bfloat16(v01); l = __float2bfloat16(v01 - __bfloat162float(h));
                g_VTh[row_c1 * SEQ + n] = h; g_VTl[row_c1 * SEQ + n] = l;
                h = __float2bfloat16(v10); l = __float2bfloat16(v10 - __bfloat162float(h));
                g_VTh[row_c0 * SEQ + n + 8] = h; g_VTl[row_c0 * SEQ + n + 8] = l;
                h = __float2bfloat16(v11); l = __float2bfloat16(v11 - __bfloat162float(h));
                g_VTh[row_c1 * SEQ + n + 8] = h; g_VTl[row_c1 * SEQ + n + 8] = l;
            }
        }
    }
}

__global__ __launch_bounds__(256, 1)
void gemm_oproj(const __nv_bfloat16* __restrict__ Ah,
                const __nv_bfloat16* __restrict__ Al,
                const __nv_bfloat16* __restrict__ Bh,
                const __nv_bfloat16* __restrict__ Bl,
                const float* __restrict__ bias, float* __restrict__ Cf) {
    extern __shared__ char sm[];
    const int tid = threadIdx.x;
    const int lane = tid & 31;
    const int warp = tid >> 5;
    const int wm = warp >> 2, wn = warp & 3;
    const size_t row0 = (size_t)blockIdx.y * 128;
    const size_t col0 = (size_t)blockIdx.x * 128;
    const uint32_t smb = smem_u32(sm);

    float acc[4][4][4];
    #pragma unroll
    for (int i = 0; i < 4; ++i)
        #pragma unroll
        for (int j = 0; j < 4; ++j)
            #pragma unroll
            for (int q = 0; q < 4; ++q) acc[i][j][q] = 0.f;

    auto issue = [&](int s, int st) {
        const int k0 = s * 64;
        const uint32_t sb = smb + st * STAGE_B2;
        #pragma unroll
        for (int p = 0; p < 4; ++p) {
            int idx = tid + p * 256;
            int r = idx >> 3, j = idx & 7;
            uint32_t d = sb + r * 144 + j * 16;
            CP_ASYNC16(d,             Ah + (row0 + r) * DIM + k0 + j * 8);
            CP_ASYNC16(d + TILE_B2,   Al + (row0 + r) * DIM + k0 + j * 8);
            CP_ASYNC16(d + 2*TILE_B2, Bh + (col0 + r) * DIM + k0 + j * 8);
            CP_ASYNC16(d + 3*TILE_B2, Bl + (col0 + r) * DIM + k0 + j * 8);
        }
        CP_COMMIT();
    };

    const int a_row_l = (lane & 15);
    const int a_col_l = (lane >> 4) << 3;
    const int b_row_l = (lane & 7) + ((lane >> 4) << 3);
    const int b_col_l = ((lane >> 3) & 1) << 3;

    issue(0, 0); issue(1, 1);
    for (int s = 0; s < 12; ++s) {
        if (s < 11) CP_WAIT1(); else CP_WAIT0();
        __syncthreads();
        if (s + 2 < 12) issue(s + 2, (s + 2) % 3);
        const uint32_t sb = smb + (s % 3) * STAGE_B2;
        const uint32_t tAh = sb, tAl = sb + TILE_B2;
        const uint32_t tBh = sb + 2 * TILE_B2, tBl = sb + 3 * TILE_B2;
        #pragma unroll
        for (int ks = 0; ks < 4; ++ks) {
            uint32_t ah[4][4], al[4][4], bh[4][2], bl[4][2];
            #pragma unroll
            for (int mi = 0; mi < 4; ++mi) {
                uint32_t off = (uint32_t)((wm * 64 + mi * 16 + a_row_l) * 144 +
                                          (ks * 16 + a_col_l) * 2);
                LDSM_X4(ah[mi][0], ah[mi][1], ah[mi][2], ah[mi][3], tAh + off);
                LDSM_X4(al[mi][0], al[mi][1], al[mi][2], al[mi][3], tAl + off);
            }
            #pragma unroll
            for (int nj = 0; nj < 2; ++nj) {
                uint32_t off = (uint32_t)((wn * 32 + nj * 16 + b_row_l) * 144 +
                                          (ks * 16 + b_col_l) * 2);
                uint32_t t0, t1, t2, t3;
                LDSM_X4(t0, t1, t2, t3, tBh + off);
                bh[nj * 2][0] = t0; bh[nj * 2][1] = t1;
                bh[nj * 2 + 1][0] = t2; bh[nj * 2 + 1][1] = t3;
                LDSM_X4(t0, t1, t2, t3, tBl + off);
                bl[nj * 2][0] = t0; bl[nj * 2][1] = t1;
                bl[nj * 2 + 1][0] = t2; bl[nj * 2 + 1][1] = t3;
            }
            #pragma unroll
            for (int mi = 0; mi < 4; ++mi)
                #pragma unroll
                for (int ni = 0; ni < 4; ++ni) {
                    MMA16816(acc[mi][ni], ah[mi], bh[ni]);
                    MMA16816(acc[mi][ni], al[mi], bh[ni]);
                    MMA16816(acc[mi][ni], ah[mi], bl[ni]);
                }
        }
    }

    const int mbase = (int)row0 + wm * 64;
    const int nbase = (int)col0 + wn * 32;
    #pragma unroll
    for (int mi = 0; mi < 4; ++mi) {
        #pragma unroll
        for (int ni = 0; ni < 4; ++ni) {
            int r = mbase + mi * 16 + (lane >> 2);
            int c = nbase + ni * 8 + (lane & 3) * 2;
            float b0 = bias[c], b1 = bias[c + 1];
            *(float2*)&Cf[(size_t)r * DIM + c] =
                make_float2(acc[mi][ni][0] + b0, acc[mi][ni][1] + b1);
            *(float2*)&Cf[(size_t)(r + 8) * DIM + c] =
                make_float2(acc[mi][ni][2] + b0, acc[mi][ni][3] + b1);
        }
    }
}

// ---------------------------------------------------------------------------
// Fused scores + softmax: 32-row x 1024-col tile, 512 threads, 3-stage K,
// single sync per chunk.
// ---------------------------------------------------------------------------
#define AF_QSZ 4608                   // 32 rows * 144 B
#define AF_Q0  0
#define AF_Q1  AF_QSZ
#define AF_K0  (2 * AF_QSZ)           // 9216
#define AF_KSZ 18432                  // 128 rows * 144 B
#define AF_KSTG (2 * AF_KSZ)          // hi+lo = 36864
#define AF_RED (AF_K0 + 3 * AF_KSTG)  // 119808
#define AF_SMEM (AF_RED + 2048)       // 121856

__global__ __launch_bounds__(512, 1)
void attn_fused(float* __restrict__ Wt) {
    extern __shared__ char sm[];
    const uint32_t smb = smem_u32(sm);
    float* red_max = (float*)(sm + AF_RED);          // [32][8]
    float* red_sum = (float*)(sm + AF_RED + 1024);   // [32][8]
    const int tid = threadIdx.x;
    const int lane = tid & 31;
    const int warp = tid >> 5;                       // 0..15
    const int wg = warp >> 3;                        // row group 0/1
    const int wn = warp & 7;                         // col owner 0..7
    const int bh = blockIdx.y;
    const int b = bh / NHEAD, h = bh - b * NHEAD;
    const size_t i0 = (size_t)blockIdx.x * 32;
    const __nv_bfloat16* Qh = g_Qh + ((size_t)b * SEQ) * DIM + h * HDIM;
    const __nv_bfloat16* Ql = g_Ql + ((size_t)b * SEQ) * DIM + h * HDIM;
    const __nv_bfloat16* Kh = g_Kh + ((size_t)b * SEQ) * DIM + h * HDIM;
    const __nv_bfloat16* Kl = g_Kl + ((size_t)b * SEQ) * DIM + h * HDIM;

    float acc[8][2][4];
    #pragma unroll
    for (int c = 0; c < 8; ++c)
        #pragma unroll
        for (int j = 0; j < 2; ++j)
            #pragma unroll
            for (int q = 0; q < 4; ++q) acc[c][j][q] = 0.f;

    auto issueK = [&](int c, int st) {
        const size_t j0n = (size_t)c * 128;
        const uint32_t kd0 = smb + AF_K0 + st * AF_KSTG;
        #pragma unroll
        for (int p = 0; p < 2; ++p) {
            int idx = tid + p * 512;
            int kr = idx >> 3, kj = idx & 7;
            uint32_t kd = kd0 + kr * 144 + kj * 16;
            CP_ASYNC16(kd,          Kh + (j0n + kr) * DIM + kj * 8);
            CP_ASYNC16(kd + AF_KSZ, Kl + (j0n + kr) * DIM + kj * 8);
        }
        CP_COMMIT();
    };

    // Q (bundled with K chunk 0's group) + K chunks 0,1
    {
        int t = tid & 255;
        int r = t >> 3, j = t & 7;
        uint32_t d = smb + ((tid < 256) ? AF_Q0 : AF_Q1) + r * 144 + j * 16;
        const __nv_bfloat16* src = (tid < 256) ? Qh : Ql;
        CP_ASYNC16(d, src + (i0 + r) * DIM + j * 8);
        issueK(0, 0);
        issueK(1, 1);
    }

    const int a_row_l = (lane & 15);
    const int a_col_l = (lane >> 4) << 3;
    const int b_row_l = (lane & 7) + ((lane >> 4) << 3);
    const int b_col_l = ((lane >> 3) & 1) << 3;

    uint32_t qh[4][4], ql[4][4];
    bool qloaded = false;

    for (int c = 0; c < 8; ++c) {
        if (c < 7) CP_WAIT1(); else CP_WAIT0();
        __syncthreads();
        if (c + 2 < 8) issueK(c + 2, (c + 2) % 3);
        if (!qloaded) {
            #pragma unroll
            for (int ks = 0; ks < 4; ++ks) {
                uint32_t off = (uint32_t)((wg * 16 + a_row_l) * 144 +
                                          (ks * 16 + a_col_l) * 2);
                LDSM_X4(qh[ks][0], qh[ks][1], qh[ks][2], qh[ks][3],
                        smb + AF_Q0 + off);
                LDSM_X4(ql[ks][0], ql[ks][1], ql[ks][2], ql[ks][3],
                        smb + AF_Q1 + off);
            }
            qloaded = true;
        }
        const uint32_t kb = smb + AF_K0 + (c % 3) * AF_KSTG;
        #pragma unroll
        for (int ks = 0; ks < 4; ++ks) {
            uint32_t bh2[2][2], bl2[2][2];
            {
                uint32_t off = (uint32_t)((wn * 16 + b_row_l) * 144 +
                                          (ks * 16 + b_col_l) * 2);
                uint32_t t0, t1, t2, t3;
                LDSM_X4(t0, t1, t2, t3, kb + off);
                bh2[0][0] = t0; bh2[0][1] = t1;
                bh2[1][0] = t2; bh2[1][1] = t3;
                LDSM_X4(t0, t1, t2, t3, kb + AF_KSZ + off);
                bl2[0][0] = t0; bl2[0][1] = t1;
                bl2[1][0] = t2; bl2[1][1] = t3;
            }
            #pragma unroll
            for (int ni = 0; ni < 2; ++ni) {
                MMA16816(acc[c][ni], qh[ks], bh2[ni]);
                MMA16816(acc[c][ni], ql[ks], bh2[ni]);
                MMA16816(acc[c][ni], qh[ks], bl2[ni]);
            }
        }
    }

    #pragma unroll
    for (int c = 0; c < 8; ++c)
        #pragma unroll
        for (int j = 0; j < 2; ++j)
            #pragma unroll
            for (int q = 0; q < 4; ++q) acc[c][j][q] *= 0.125f;

    const int R0 = wg * 16 + (lane >> 2);
    const int R1 = R0 + 8;

    float m0 = -1e30f, m1 = -1e30f;
    #pragma unroll
    for (int c = 0; c < 8; ++c)
        #pragma unroll
        for (int j = 0; j < 2; ++j) {
            m0 = fmaxf(m0, fmaxf(acc[c][j][0], acc[c][j][1]));
            m1 = fmaxf(m1, fmaxf(acc[c][j][2], acc[c][j][3]));
        }
    m0 = fmaxf(m0, __shfl_xor_sync(~0u, m0, 1));
    m0 = fmaxf(m0, __shfl_xor_sync(~0u, m0, 2));
    m1 = fmaxf(m1, __shfl_xor_sync(~0u, m1, 1));
    m1 = fmaxf(m1, __shfl_xor_sync(~0u, m1, 2));
    if ((lane & 3) == 0) {
        red_max[R0 * 8 + wn] = m0;
        red_max[R1 * 8 + wn] = m1;
    }
    __syncthreads();
    m0 = red_max[R0 * 8];
    m1 = red_max[R1 * 8];
    #pragma unroll
    for (int i = 1; i < 8; ++i) {
        m0 = fmaxf(m0, red_max[R0 * 8 + i]);
        m1 = fmaxf(m1, red_max[R1 * 8 + i]);
    }

    float s0 = 0.f, s1 = 0.f;
    #pragma unroll
    for (int c = 0; c < 8; ++c)
        #pragma unroll
        for (int j = 0; j < 2; ++j) {
            acc[c][j][0] = __expf(acc[c][j][0] - m0);
            acc[c][j][1] = __expf(acc[c][j][1] - m0);
            acc[c][j][2] = __expf(acc[c][j][2] - m1);
            acc[c][j][3] = __expf(acc[c][j][3] - m1);
            s0 += acc[c][j][0] + acc[c][j][1];
            s1 += acc[c][j][2] + acc[c][j][3];
        }
    s0 += __shfl_xor_sync(~0u, s0, 1);
    s0 += __shfl_xor_sync(~0u, s0, 2);
    s1 += __shfl_xor_sync(~0u, s1, 1);
    s1 += __shfl_xor_sync(~0u, s1, 2);
    if ((lane & 3) == 0) {
        red_sum[R0 * 8 + wn] = s0;
        red_sum[R1 * 8 + wn] = s1;
    }
    __syncthreads();
    s0 = 0.f; s1 = 0.f;
    #pragma unroll
    for (int i = 0; i < 8; ++i) {
        s0 += red_sum[R0 * 8 + i];
        s1 += red_sum[R1 * 8 + i];
    }
    float inv0 = 1.0f / s0, inv1 = 1.0f / s1;

    float* Wb = Wt + ((size_t)bh * SEQ + i0) * SEQ;
    #pragma unroll
    for (int c = 0; c < 8; ++c)
        #pragma unroll
        for (int j = 0; j < 2; ++j) {
            int col = c * 128 + wn * 16 + j * 8 + (lane & 3) * 2;
            *(float2*)&Wb[(size_t)R0 * SEQ + col] =
                make_float2(acc[c][j][0] * inv0, acc[c][j][1] * inv0);
            *(float2*)&Wb[(size_t)R1 * SEQ + col] =
                make_float2(acc[c][j][2] * inv1, acc[c][j][3] * inv1);
        }
}

// ---------------------------------------------------------------------------
// O = P @ V (256x64 tile, proven config). fp32 P in-kernel split; VT cp.async.
// ---------------------------------------------------------------------------
#define AV_ATILE 20480
#define AV_BTILE 5120
#define AV_ASTG  (2 * AV_ATILE)
#define AV_BSTG  (2 * AV_BTILE)
#define AV_B0    (2 * AV_ASTG)
#define AV_SMEM  (2 * AV_ASTG + 2 * AV_BSTG)

__global__ __launch_bounds__(256, 1)
void av_mma(const float* __restrict__ Wt) {
    extern __shared__ char sm[];
    const int tid = threadIdx.x;
    const int lane = tid & 31;
    const int warp = tid >> 5;
    const int wm = warp >> 1, wn = warp & 1;
    const int bh = blockIdx.z;
    const int b = bh / NHEAD, h = bh - b * NHEAD;
    const size_t m0 = (size_t)blockIdx.y * 256;
    const uint32_t smb = smem_u32(sm);
    const float* P = Wt + ((size_t)bh * SEQ + m0) * SEQ;
    const __nv_bfloat16* Bh = g_VTh + (size_t)bh * HDIM * SEQ;
    const __nv_bfloat16* Bl = g_VTl + (size_t)bh * HDIM * SEQ;

    float acc[4][4][4];
    #pragma unroll
    for (int i = 0; i < 4; ++i)
        #pragma unroll
        for (int j = 0; j < 4; ++j)
            #pragma unroll
            for (int q = 0; q < 4; ++q) acc[i][j][q] = 0.f;

    const int ar = tid >> 3, aj = tid & 7;

    auto issueB = [&](int s, int st) {
        const int k0 = s * 32;
        int r = tid >> 2, j = tid & 3;
        if (r < 64) {
            uint32_t d = smb + AV_B0 + st * AV_BSTG + r * 80 + j * 16;
            CP_ASYNC16(d,            Bh + (size_t)r * SEQ + k0 + j * 8);
            CP_ASYNC16(d + AV_BTILE, Bl + (size_t)r * SEQ + k0 + j * 8);
        }
        CP_COMMIT();
    };

    float4 areg[8];
    auto ldgA = [&](int s) {
        const int k0 = s * 32;
        #pragma unroll
        for (int g = 0; g < 8; ++g)
            areg[g] = *(const float4*)&P[(size_t)(ar + 32 * g) * SEQ + k0 + aj * 4];
    };

    const int a_row_l = (lane & 15);
    const int a_col_l = (lane >> 4) << 3;
    const int b_row_l = (lane & 7) + ((lane >> 4) << 3);
    const int b_col_l = ((lane >> 3) & 1) << 3;

    issueB(0, 0);
    issueB(1, 1);
    ldgA(0);
    for (int s = 0; s < 32; ++s) {
        {
            const uint32_t ab = smb + (s & 1) * AV_ASTG;
            #pragma unroll
            for (int g = 0; g < 8; ++g) {
                float4 v = areg[g];
                __nv_bfloat162 lo0, lo1;
                __nv_bfloat162 hi0 = split_hi2(v.x, v.y, lo0);
                __nv_bfloat162 hi1 = split_hi2(v.z, v.w, lo1);
                uint32_t off = (ab - smb) + (ar + 32 * g) * 80 + aj * 8;
                *(__nv_bfloat162*)(sm + off)                = hi0;
                *(__nv_bfloat162*)(sm + off + 4)            = hi1;
                *(__nv_bfloat162*)(sm + off + AV_ATILE)     = lo0;
                *(__nv_bfloat162*)(sm + off + AV_ATILE + 4) = lo1;
            }
        }
        if (s < 31) CP_WAIT1(); else CP_WAIT0();
        __syncthreads();
        if (s + 1 < 32) ldgA(s + 1);

        const uint32_t ab = smb + (s & 1) * AV_ASTG;
        const uint32_t tAh = ab, tAl = ab + AV_ATILE;
        const uint32_t bb = smb + AV_B0 + (s & 1) * AV_BSTG;
        const uint32_t tBh = bb, tBl = bb + AV_BTILE;
        #pragma unroll
        for (int ks = 0; ks < 2; ++ks) {
            uint32_t ah[4][4], al[4][4], bh2[4][2], bl2[4][2];
            #pragma unroll
            for (int mi = 0; mi < 4; ++mi) {
                uint32_t off = (uint32_t)((wm * 64 + mi * 16 + a_row_l) * 80 +
                                          (ks * 16 + a_col_l) * 2);
                LDSM_X4(ah[mi][0], ah[mi][1], ah[mi][2], ah[mi][3], tAh + off);
                LDSM_X4(al[mi][0], al[mi][1], al[mi][2], al[mi][3], tAl + off);
            }
            #pragma unroll
            for (int nj = 0; nj < 2; ++nj) {
                uint32_t off = (uint32_t)((wn * 32 + nj * 16 + b_row_l) * 80 +
                                          (ks * 16 + b_col_l) * 2);
                uint32_t t0, t1, t2, t3;
                LDSM_X4(t0, t1, t2, t3, tBh + off);
                bh2[nj * 2][0] = t0; bh2[nj * 2][1] = t1;
                bh2[nj * 2 + 1][0] = t2; bh2[nj * 2 + 1][1] = t3;
                LDSM_X4(t0, t1, t2, t3, tBl + off);
                bl2[nj * 2][0] = t0; bl2[nj * 2][1] = t1;
                bl2[nj * 2 + 1][0] = t2; bl2[nj * 2 + 1][1] = t3;
            }
            #pragma unroll
            for (int mi = 0; mi < 4; ++mi)
                #pragma unroll
                for (int ni = 0; ni < 4; ++ni) {
                    MMA16816(acc[mi][ni], ah[mi], bh2[ni]);
                    MMA16816(acc[mi][ni], al[mi], bh2[ni]);
                    MMA16816(acc[mi][ni], ah[mi], bl2[ni]);
                }
        }
        __syncthreads();
        if (s + 2 < 32) issueB(s + 2, (s) & 1);
    }

    #pragma unroll
    for (int mi = 0; mi < 4; ++mi) {
        #pragma unroll
        for (int ni = 0; ni < 4; ++ni) {
            int rl = wm * 64 + mi * 16 + (lane >> 2);
            int cl = wn * 32 + ni * 8 + (lane & 3) * 2;
            size_t r = (size_t)b * SEQ + m0 + rl;
            size_t c = h * HDIM + cl;
            __nv_bfloat162 lo0, lo1;
            __nv_bfloat162 hi0 = split_hi2(acc[mi][ni][0], acc[mi][ni][1], lo0);
            __nv_bfloat162 hi1 = split_hi2(acc[mi][ni][2], acc[mi][ni][3], lo1);
            *(__nv_bfloat162*)&g_Oh[r * DIM + c] = hi0;
            *(__nv_bfloat162*)&g_Ol[r * DIM + c] = lo0;
            *(__nv_bfloat162*)&g_Oh[(r + 8) * DIM + c] = hi1;
            *(__nv_bfloat162*)&g_Ol[(r + 8) * DIM + c] = lo1;
        }
    }
}

// ---------------------------------------------------------------------------
extern "C" void kernel_launch(void* const* d_in, const int* in_sizes, int n_in,
                              void* d_out, int out_size) {
    const float* x  = (const float*)d_in[0];
    const float* Wq = (const float*)d_in[1];
    const float* bq = (const float*)d_in[2];
    const float* Wk = (const float*)d_in[3];
    const float* bk = (const float*)d_in[4];
    const float* Wv = (const float*)d_in[5];
    const float* bv = (const float*)d_in[6];
    const float* Wo = (const float*)d_in[7];
    const float* bo = (const float*)d_in[8];

    float* out = (float*)d_out;
    float* wts = out + OUT_OFF;

    cudaFuncSetAttribute(gemm_qkv,
                         cudaFuncAttributeMaxDynamicSharedMemorySize, GSMEM3S);
    cudaFuncSetAttribute(gemm_oproj,
                         cudaFuncAttributeMaxDynamicSharedMemorySize, GSMEM3S);
    cudaFuncSetAttribute(attn_fused,
                         cudaFuncAttributeMaxDynamicSharedMemorySize, AF_SMEM);
    cudaFuncSetAttribute(av_mma,
                         cudaFuncAttributeMaxDynamicSharedMemorySize, AV_SMEM);

    __nv_bfloat16 *Xh, *Xl, *Oh, *Ol, *WTh, *WTl;
    cudaGetSymbolAddress((void**)&Xh, g_Xh);
    cudaGetSymbolAddress((void**)&Xl, g_Xl);
    cudaGetSymbolAddress((void**)&Oh, g_Oh);
    cudaGetSymbolAddress((void**)&Ol, g_Ol);
    cudaGetSymbolAddress((void**)&WTh, g_WTh);
    cudaGetSymbolAddress((void**)&WTl, g_WTl);

    const int NELEM = MROWS * DIM;
    split_kernel<<<NELEM / 4 / 256, 256>>>(x, Xh, Xl, NELEM / 4);
    splitT4<<<dim3(DIM / 32, DIM / 32, 4), dim3(32, 8)>>>(Wq, Wk, Wv, Wo,
                                                          WTh, WTl);

    gemm_qkv<<<dim3(18, MROWS / 128), 256, GSMEM3S>>>(bq, bk, bv);

    attn_fused<<<dim3(SEQ / 32, BH), 512, AF_SMEM>>>(wts);
    av_mma<<<dim3(1, SEQ / 256, BH), 256, AV_SMEM>>>(wts);

    gemm_oproj<<<dim3(DIM / 128, MROWS / 128), 256, GSMEM3S>>>(
        Oh, Ol, WTh + 3 * DIM * DIM, WTl + 3 * DIM * DIM, bo, out);
}

// round 16
// speedup vs baseline: 1.1759x; 1.0192x over previous
#include <cuda_runtime.h>
#include <cuda_bf16.h>
#include <cstdint>

#define BATCH 8
#define SEQ   1024
#define DIM   768
#define NHEAD 12
#define HDIM  64
#define BH    (BATCH * NHEAD)     // 96
#define MROWS (BATCH * SEQ)       // 8192
#define OUT_OFF ((size_t)MROWS * DIM)

// ---------------- scratch (__device__ globals; no allocs allowed) ----------
__device__ __nv_bfloat16 g_Xh[MROWS * DIM];
__device__ __nv_bfloat16 g_Xl[MROWS * DIM];
__device__ __nv_bfloat16 g_Qh[MROWS * DIM];
__device__ __nv_bfloat16 g_Ql[MROWS * DIM];
__device__ __nv_bfloat16 g_Kh[MROWS * DIM];
__device__ __nv_bfloat16 g_Kl[MROWS * DIM];
__device__ __nv_bfloat16 g_VTh[BH * HDIM * SEQ];  // [bh*64+d][n]
__device__ __nv_bfloat16 g_VTl[BH * HDIM * SEQ];
__device__ __nv_bfloat16 g_Oh[MROWS * DIM];
__device__ __nv_bfloat16 g_Ol[MROWS * DIM];
__device__ __nv_bfloat16 g_WTh[4 * DIM * DIM];    // W^T hi: [q;k;v;o] rows
__device__ __nv_bfloat16 g_WTl[4 * DIM * DIM];

// ---------------- helpers --------------------------------------------------
__device__ __forceinline__ uint32_t smem_u32(const void* p) {
    uint32_t a;
    asm("{ .reg .u64 t; cvta.to.shared.u64 t, %1; cvt.u32.u64 %0, t; }"
        : "=r"(a) : "l"(p));
    return a;
}
#define CP_ASYNC16(sm, gp) \
    asm volatile("cp.async.cg.shared.global [%0], [%1], 16;" \
                 :: "r"(sm), "l"(gp) : "memory")
#define CP_COMMIT() asm volatile("cp.async.commit_group;" ::: "memory")
#define CP_WAIT1()  asm volatile("cp.async.wait_group 1;" ::: "memory")
#define CP_WAIT0()  asm volatile("cp.async.wait_group 0;" ::: "memory")
#define LDSM_X4(r0, r1, r2, r3, addr) \
    asm volatile("ldmatrix.sync.aligned.m8n8.x4.shared.b16 {%0,%1,%2,%3}, [%4];" \
                 : "=r"(r0), "=r"(r1), "=r"(r2), "=r"(r3) : "r"(addr))
#define MMA16816(d, a, b) \
    asm volatile("mma.sync.aligned.m16n8k16.row.col.f32.bf16.bf16.f32 " \
                 "{%0,%1,%2,%3}, {%4,%5,%6,%7}, {%8,%9}, {%0,%1,%2,%3};" \
                 : "+f"((d)[0]), "+f"((d)[1]), "+f"((d)[2]), "+f"((d)[3]) \
                 : "r"((a)[0]), "r"((a)[1]), "r"((a)[2]), "r"((a)[3]), \
                   "r"((b)[0]), "r"((b)[1]))

__device__ __forceinline__ __nv_bfloat162 split_hi2(float a, float b,
                                                    __nv_bfloat162& lo) {
    __nv_bfloat16 h0 = __float2bfloat16(a);
    __nv_bfloat16 h1 = __float2bfloat16(b);
    lo.x = __float2bfloat16(a - __bfloat162float(h0));
    lo.y = __float2bfloat16(b - __bfloat162float(h1));
    __nv_bfloat162 hi; hi.x = h0; hi.y = h1;
    return hi;
}

// ---------------------------------------------------------------------------
__global__ void split_kernel(const float* __restrict__ src,
                             __nv_bfloat16* __restrict__ hi,
                             __nv_bfloat16* __restrict__ lo, int n4) {
    int i = blockIdx.x * blockDim.x + threadIdx.x;
    if (i >= n4) return;
    float4 v = reinterpret_cast<const float4*>(src)[i];
    __nv_bfloat162 l0, l1;
    __nv_bfloat162 h0 = split_hi2(v.x, v.y, l0);
    __nv_bfloat162 h1 = split_hi2(v.z, v.w, l1);
    reinterpret_cast<__nv_bfloat162*>(hi)[2 * i]     = h0;
    reinterpret_cast<__nv_bfloat162*>(hi)[2 * i + 1] = h1;
    reinterpret_cast<__nv_bfloat162*>(lo)[2 * i]     = l0;
    reinterpret_cast<__nv_bfloat162*>(lo)[2 * i + 1] = l1;
}

__global__ void splitT4(const float* __restrict__ W0, const float* __restrict__ W1,
                        const float* __restrict__ W2, const float* __restrict__ W3,
                        __nv_bfloat16* __restrict__ hiT,
                        __nv_bfloat16* __restrict__ loT) {
    __shared__ float t[32][33];
    int z = blockIdx.z;
    const float* W = (z == 0) ? W0 : (z == 1) ? W1 : (z == 2) ? W2 : W3;
    size_t zoff = (size_t)z * DIM * DIM;
    int n0 = blockIdx.x * 32, k0 = blockIdx.y * 32;
    int tx = threadIdx.x, ty = threadIdx.y;           // (32, 8)
    #pragma unroll
    for (int i = 0; i < 4; ++i)
        t[ty * 4 + i][tx] = W[(size_t)(k0 + ty * 4 + i) * DIM + n0 + tx];
    __syncthreads();
    #pragma unroll
    for (int i = 0; i < 4; ++i) {
        int n = n0 + ty * 4 + i, k = k0 + tx;
        float a = t[tx][ty * 4 + i];
        __nv_bfloat16 h = __float2bfloat16(a);
        hiT[zoff + (size_t)n * DIM + k] = h;
        loT[zoff + (size_t)n * DIM + k] = __float2bfloat16(a - __bfloat162float(h));
    }
}

// ---------------------------------------------------------------------------
// GEMM tiles: 128x128, K-slab 64, 3-stage, single-sync mainloop.
// ---------------------------------------------------------------------------
#define TILE_B2  18432                 // 128 rows * 144 B
#define STAGE_B2 (4 * TILE_B2)         // 73728
#define GSMEM3S  (3 * STAGE_B2)        // 221184

__global__ __launch_bounds__(256, 1)
void gemm_qkv(const float* __restrict__ bq, const float* __restrict__ bk,
              const float* __restrict__ bv) {
    extern __shared__ char sm[];
    const int tid = threadIdx.x;
    const int lane = tid & 31;
    const int warp = tid >> 5;
    const int wm = warp >> 2, wn = warp & 3;
    const size_t row0 = (size_t)blockIdx.y * 128;
    const int bx = blockIdx.x;
    const int sel = bx / 6;
    const size_t col0g = (size_t)bx * 128;
    const int col0l = (bx - sel * 6) * 128;
    const uint32_t smb = smem_u32(sm);
    const float* bias = (sel == 0) ? bq : (sel == 1) ? bk : bv;

    float acc[4][4][4];
    #pragma unroll
    for (int i = 0; i < 4; ++i)
        #pragma unroll
        for (int j = 0; j < 4; ++j)
            #pragma unroll
            for (int q = 0; q < 4; ++q) acc[i][j][q] = 0.f;

    auto issue = [&](int s, int st) {
        const int k0 = s * 64;
        const uint32_t sb = smb + st * STAGE_B2;
        #pragma unroll
        for (int p = 0; p < 4; ++p) {
            int idx = tid + p * 256;
            int r = idx >> 3, j = idx & 7;
            uint32_t d = sb + r * 144 + j * 16;
            CP_ASYNC16(d,             g_Xh + (row0 + r) * DIM + k0 + j * 8);
            CP_ASYNC16(d + TILE_B2,   g_Xl + (row0 + r) * DIM + k0 + j * 8);
            CP_ASYNC16(d + 2*TILE_B2, g_WTh + (col0g + r) * DIM + k0 + j * 8);
            CP_ASYNC16(d + 3*TILE_B2, g_WTl + (col0g + r) * DIM + k0 + j * 8);
        }
        CP_COMMIT();
    };

    const int a_row_l = (lane & 15);
    const int a_col_l = (lane >> 4) << 3;
    const int b_row_l = (lane & 7) + ((lane >> 4) << 3);
    const int b_col_l = ((lane >> 3) & 1) << 3;

    issue(0, 0); issue(1, 1);
    for (int s = 0; s < 12; ++s) {
        if (s < 11) CP_WAIT1(); else CP_WAIT0();
        __syncthreads();
        if (s + 2 < 12) issue(s + 2, (s + 2) % 3);
        const uint32_t sb = smb + (s % 3) * STAGE_B2;
        const uint32_t tAh = sb, tAl = sb + TILE_B2;
        const uint32_t tBh = sb + 2 * TILE_B2, tBl = sb + 3 * TILE_B2;
        #pragma unroll
        for (int ks = 0; ks < 4; ++ks) {
            uint32_t ah[4][4], al[4][4], bh[4][2], bl[4][2];
            #pragma unroll
            for (int mi = 0; mi < 4; ++mi) {
                uint32_t off = (uint32_t)((wm * 64 + mi * 16 + a_row_l) * 144 +
                                          (ks * 16 + a_col_l) * 2);
                LDSM_X4(ah[mi][0], ah[mi][1], ah[mi][2], ah[mi][3], tAh + off);
                LDSM_X4(al[mi][0], al[mi][1], al[mi][2], al[mi][3], tAl + off);
            }
            #pragma unroll
            for (int nj = 0; nj < 2; ++nj) {
                uint32_t off = (uint32_t)((wn * 32 + nj * 16 + b_row_l) * 144 +
                                          (ks * 16 + b_col_l) * 2);
                uint32_t t0, t1, t2, t3;
                LDSM_X4(t0, t1, t2, t3, tBh + off);
                bh[nj * 2][0] = t0; bh[nj * 2][1] = t1;
                bh[nj * 2 + 1][0] = t2; bh[nj * 2 + 1][1] = t3;
                LDSM_X4(t0, t1, t2, t3, tBl + off);
                bl[nj * 2][0] = t0; bl[nj * 2][1] = t1;
                bl[nj * 2 + 1][0] = t2; bl[nj * 2 + 1][1] = t3;
            }
            #pragma unroll
            for (int mi = 0; mi < 4; ++mi)
                #pragma unroll
                for (int ni = 0; ni < 4; ++ni) {
                    MMA16816(acc[mi][ni], ah[mi], bh[ni]);
                    MMA16816(acc[mi][ni], al[mi], bh[ni]);
                    MMA16816(acc[mi][ni], ah[mi], bl[ni]);
                }
        }
    }

    __nv_bfloat16* Ch = (sel == 0) ? g_Qh : g_Kh;
    __nv_bfloat16* Cl = (sel == 0) ? g_Ql : g_Kl;
    const int mbase = (int)row0 + wm * 64;
    const int nbase = col0l + wn * 32;
    #pragma unroll
    for (int mi = 0; mi < 4; ++mi) {
        #pragma unroll
        for (int ni = 0; ni < 4; ++ni) {
            int r = mbase + mi * 16 + (lane >> 2);
            int c = nbase + ni * 8 + (lane & 3) * 2;
            float b0 = bias[c], b1 = bias[c + 1];
            float v00 = acc[mi][ni][0] + b0, v01 = acc[mi][ni][1] + b1;
            float v10 = acc[mi][ni][2] + b0, v11 = acc[mi][ni][3] + b1;
            if (sel < 2) {
                __nv_bfloat162 lo0, lo1;
                __nv_bfloat162 hi0 = split_hi2(v00, v01, lo0);
                __nv_bfloat162 hi1 = split_hi2(v10, v11, lo1);
                *(__nv_bfloat162*)&Ch[(size_t)r * DIM + c] = hi0;
                *(__nv_bfloat162*)&Cl[(size_t)r * DIM + c] = lo0;
                *(__nv_bfloat162*)&Ch[(size_t)(r + 8) * DIM + c] = hi1;
                *(__nv_bfloat162*)&Cl[(size_t)(r + 8) * DIM + c] = lo1;
            } else {
                int b = r >> 10, n = r & 1023;
                size_t row_c0 = ((size_t)b * NHEAD + (c >> 6)) * HDIM + (c & 63);
                size_t row_c1 = ((size_t)b * NHEAD + ((c + 1) >> 6)) * HDIM + ((c + 1) & 63);
                __nv_bfloat16 h, l;
                h = __float2bfloat16(v00); l = __float2bfloat16(v00 - __bfloat162float(h));
                g_VTh[row_c0 * SEQ + n] = h; g_VTl[row_c0 * SEQ + n] = l;
                h = __float2bfloat16(v01); l = __float2bfloat16(v01 - __bfloat162float(h));
                g_VTh[row_c1 * SEQ + n] = h; g_VTl[row_c1 * SEQ + n] = l;
                h = __float2bfloat16(v10); l = __float2bfloat16(v10 - __bfloat162float(h));
                g_VTh[row_c0 * SEQ + n + 8] = h; g_VTl[row_c0 * SEQ + n + 8] = l;
                h = __float2bfloat16(v11); l = __float2bfloat16(v11 - __bfloat162float(h));
                g_VTh[row_c1 * SEQ + n + 8] = h; g_VTl[row_c1 * SEQ + n + 8] = l;
            }
        }
    }
}

__global__ __launch_bounds__(256, 1)
void gemm_oproj(const __nv_bfloat16* __restrict__ Ah,
                const __nv_bfloat16* __restrict__ Al,
                const __nv_bfloat16* __restrict__ Bh,
                const __nv_bfloat16* __restrict__ Bl,
                const float* __restrict__ bias, float* __restrict__ Cf) {
    extern __shared__ char sm[];
    const int tid = threadIdx.x;
    const int lane = tid & 31;
    const int warp = tid >> 5;
    const int wm = warp >> 2, wn = warp & 3;
    const size_t row0 = (size_t)blockIdx.y * 128;
    const size_t col0 = (size_t)blockIdx.x * 128;
    const uint32_t smb = smem_u32(sm);

    float acc[4][4][4];
    #pragma unroll
    for (int i = 0; i < 4; ++i)
        #pragma unroll
        for (int j = 0; j < 4; ++j)
            #pragma unroll
            for (int q = 0; q < 4; ++q) acc[i][j][q] = 0.f;

    auto issue = [&](int s, int st) {
        const int k0 = s * 64;
        const uint32_t sb = smb + st * STAGE_B2;
        #pragma unroll
        for (int p = 0; p < 4; ++p) {
            int idx = tid + p * 256;
            int r = idx >> 3, j = idx & 7;
            uint32_t d = sb + r * 144 + j * 16;
            CP_ASYNC16(d,             Ah + (row0 + r) * DIM + k0 + j * 8);
            CP_ASYNC16(d + TILE_B2,   Al + (row0 + r) * DIM + k0 + j * 8);
            CP_ASYNC16(d + 2*TILE_B2, Bh + (col0 + r) * DIM + k0 + j * 8);
            CP_ASYNC16(d + 3*TILE_B2, Bl + (col0 + r) * DIM + k0 + j * 8);
        }
        CP_COMMIT();
    };

    const int a_row_l = (lane & 15);
    const int a_col_l = (lane >> 4) << 3;
    const int b_row_l = (lane & 7) + ((lane >> 4) << 3);
    const int b_col_l = ((lane >> 3) & 1) << 3;

    issue(0, 0); issue(1, 1);
    for (int s = 0; s < 12; ++s) {
        if (s < 11) CP_WAIT1(); else CP_WAIT0();
        __syncthreads();
        if (s + 2 < 12) issue(s + 2, (s + 2) % 3);
        const uint32_t sb = smb + (s % 3) * STAGE_B2;
        const uint32_t tAh = sb, tAl = sb + TILE_B2;
        const uint32_t tBh = sb + 2 * TILE_B2, tBl = sb + 3 * TILE_B2;
        #pragma unroll
        for (int ks = 0; ks < 4; ++ks) {
            uint32_t ah[4][4], al[4][4], bh[4][2], bl[4][2];
            #pragma unroll
            for (int mi = 0; mi < 4; ++mi) {
                uint32_t off = (uint32_t)((wm * 64 + mi * 16 + a_row_l) * 144 +
                                          (ks * 16 + a_col_l) * 2);
                LDSM_X4(ah[mi][0], ah[mi][1], ah[mi][2], ah[mi][3], tAh + off);
                LDSM_X4(al[mi][0], al[mi][1], al[mi][2], al[mi][3], tAl + off);
            }
            #pragma unroll
            for (int nj = 0; nj < 2; ++nj) {
                uint32_t off = (uint32_t)((wn * 32 + nj * 16 + b_row_l) * 144 +
                                          (ks * 16 + b_col_l) * 2);
                uint32_t t0, t1, t2, t3;
                LDSM_X4(t0, t1, t2, t3, tBh + off);
                bh[nj * 2][0] = t0; bh[nj * 2][1] = t1;
                bh[nj * 2 + 1][0] = t2; bh[nj * 2 + 1][1] = t3;
                LDSM_X4(t0, t1, t2, t3, tBl + off);
                bl[nj * 2][0] = t0; bl[nj * 2][1] = t1;
                bl[nj * 2 + 1][0] = t2; bl[nj * 2 + 1][1] = t3;
            }
            #pragma unroll
            for (int mi = 0; mi < 4; ++mi)
                #pragma unroll
                for (int ni = 0; ni < 4; ++ni) {
                    MMA16816(acc[mi][ni], ah[mi], bh[ni]);
                    MMA16816(acc[mi][ni], al[mi], bh[ni]);
                    MMA16816(acc[mi][ni], ah[mi], bl[ni]);
                }
        }
    }

    const int mbase = (int)row0 + wm * 64;
    const int nbase = (int)col0 + wn * 32;
    #pragma unroll
    for (int mi = 0; mi < 4; ++mi) {
        #pragma unroll
        for (int ni = 0; ni < 4; ++ni) {
            int r = mbase + mi * 16 + (lane >> 2);
            int c = nbase + ni * 8 + (lane & 3) * 2;
            float b0 = bias[c], b1 = bias[c + 1];
            *(float2*)&Cf[(size_t)r * DIM + c] =
                make_float2(acc[mi][ni][0] + b0, acc[mi][ni][1] + b1);
            *(float2*)&Cf[(size_t)(r + 8) * DIM + c] =
                make_float2(acc[mi][ni][2] + b0, acc[mi][ni][3] + b1);
        }
    }
}

// ---------------------------------------------------------------------------
// Fused scores + softmax: 32-row x 1024-col tile, 512 threads, 3-stage K,
// single sync per chunk. Proven R15 config.
// ---------------------------------------------------------------------------
#define AF_QSZ 4608
#define AF_Q0  0
#define AF_Q1  AF_QSZ
#define AF_K0  (2 * AF_QSZ)           // 9216
#define AF_KSZ 18432
#define AF_KSTG (2 * AF_KSZ)          // 36864
#define AF_RED (AF_K0 + 3 * AF_KSTG)  // 119808
#define AF_SMEM (AF_RED + 2048)       // 121856

__global__ __launch_bounds__(512, 1)
void attn_fused(float* __restrict__ Wt) {
    extern __shared__ char sm[];
    const uint32_t smb = smem_u32(sm);
    float* red_max = (float*)(sm + AF_RED);
    float* red_sum = (float*)(sm + AF_RED + 1024);
    const int tid = threadIdx.x;
    const int lane = tid & 31;
    const int warp = tid >> 5;
    const int wg = warp >> 3;
    const int wn = warp & 7;
    const int bh = blockIdx.y;
    const int b = bh / NHEAD, h = bh - b * NHEAD;
    const size_t i0 = (size_t)blockIdx.x * 32;
    const __nv_bfloat16* Qh = g_Qh + ((size_t)b * SEQ) * DIM + h * HDIM;
    const __nv_bfloat16* Ql = g_Ql + ((size_t)b * SEQ) * DIM + h * HDIM;
    const __nv_bfloat16* Kh = g_Kh + ((size_t)b * SEQ) * DIM + h * HDIM;
    const __nv_bfloat16* Kl = g_Kl + ((size_t)b * SEQ) * DIM + h * HDIM;

    float acc[8][2][4];
    #pragma unroll
    for (int c = 0; c < 8; ++c)
        #pragma unroll
        for (int j = 0; j < 2; ++j)
            #pragma unroll
            for (int q = 0; q < 4; ++q) acc[c][j][q] = 0.f;

    auto issueK = [&](int c, int st) {
        const size_t j0n = (size_t)c * 128;
        const uint32_t kd0 = smb + AF_K0 + st * AF_KSTG;
        #pragma unroll
        for (int p = 0; p < 2; ++p) {
            int idx = tid + p * 512;
            int kr = idx >> 3, kj = idx & 7;
            uint32_t kd = kd0 + kr * 144 + kj * 16;
            CP_ASYNC16(kd,          Kh + (j0n + kr) * DIM + kj * 8);
            CP_ASYNC16(kd + AF_KSZ, Kl + (j0n + kr) * DIM + kj * 8);
        }
        CP_COMMIT();
    };

    {
        int t = tid & 255;
        int r = t >> 3, j = t & 7;
        uint32_t d = smb + ((tid < 256) ? AF_Q0 : AF_Q1) + r * 144 + j * 16;
        const __nv_bfloat16* src = (tid < 256) ? Qh : Ql;
        CP_ASYNC16(d, src + (i0 + r) * DIM + j * 8);
        issueK(0, 0);
        issueK(1, 1);
    }

    const int a_row_l = (lane & 15);
    const int a_col_l = (lane >> 4) << 3;
    const int b_row_l = (lane & 7) + ((lane >> 4) << 3);
    const int b_col_l = ((lane >> 3) & 1) << 3;

    uint32_t qh[4][4], ql[4][4];
    bool qloaded = false;

    for (int c = 0; c < 8; ++c) {
        if (c < 7) CP_WAIT1(); else CP_WAIT0();
        __syncthreads();
        if (c + 2 < 8) issueK(c + 2, (c + 2) % 3);
        if (!qloaded) {
            #pragma unroll
            for (int ks = 0; ks < 4; ++ks) {
                uint32_t off = (uint32_t)((wg * 16 + a_row_l) * 144 +
                                          (ks * 16 + a_col_l) * 2);
                LDSM_X4(qh[ks][0], qh[ks][1], qh[ks][2], qh[ks][3],
                        smb + AF_Q0 + off);
                LDSM_X4(ql[ks][0], ql[ks][1], ql[ks][2], ql[ks][3],
                        smb + AF_Q1 + off);
            }
            qloaded = true;
        }
        const uint32_t kb = smb + AF_K0 + (c % 3) * AF_KSTG;
        #pragma unroll
        for (int ks = 0; ks < 4; ++ks) {
            uint32_t bh2[2][2], bl2[2][2];
            {
                uint32_t off = (uint32_t)((wn * 16 + b_row_l) * 144 +
                                          (ks * 16 + b_col_l) * 2);
                uint32_t t0, t1, t2, t3;
                LDSM_X4(t0, t1, t2, t3, kb + off);
                bh2[0][0] = t0; bh2[0][1] = t1;
                bh2[1][0] = t2; bh2[1][1] = t3;
                LDSM_X4(t0, t1, t2, t3, kb + AF_KSZ + off);
                bl2[0][0] = t0; bl2[0][1] = t1;
                bl2[1][0] = t2; bl2[1][1] = t3;
            }
            #pragma unroll
            for (int ni = 0; ni < 2; ++ni) {
                MMA16816(acc[c][ni], qh[ks], bh2[ni]);
                MMA16816(acc[c][ni], ql[ks], bh2[ni]);
                MMA16816(acc[c][ni], qh[ks], bl2[ni]);
            }
        }
    }

    #pragma unroll
    for (int c = 0; c < 8; ++c)
        #pragma unroll
        for (int j = 0; j < 2; ++j)
            #pragma unroll
            for (int q = 0; q < 4; ++q) acc[c][j][q] *= 0.125f;

    const int R0 = wg * 16 + (lane >> 2);
    const int R1 = R0 + 8;

    float m0 = -1e30f, m1 = -1e30f;
    #pragma unroll
    for (int c = 0; c < 8; ++c)
        #pragma unroll
        for (int j = 0; j < 2; ++j) {
            m0 = fmaxf(m0, fmaxf(acc[c][j][0], acc[c][j][1]));
            m1 = fmaxf(m1, fmaxf(acc[c][j][2], acc[c][j][3]));
        }
    m0 = fmaxf(m0, __shfl_xor_sync(~0u, m0, 1));
    m0 = fmaxf(m0, __shfl_xor_sync(~0u, m0, 2));
    m1 = fmaxf(m1, __shfl_xor_sync(~0u, m1, 1));
    m1 = fmaxf(m1, __shfl_xor_sync(~0u, m1, 2));
    if ((lane & 3) == 0) {
        red_max[R0 * 8 + wn] = m0;
        red_max[R1 * 8 + wn] = m1;
    }
    __syncthreads();
    m0 = red_max[R0 * 8];
    m1 = red_max[R1 * 8];
    #pragma unroll
    for (int i = 1; i < 8; ++i) {
        m0 = fmaxf(m0, red_max[R0 * 8 + i]);
        m1 = fmaxf(m1, red_max[R1 * 8 + i]);
    }

    float s0 = 0.f, s1 = 0.f;
    #pragma unroll
    for (int c = 0; c < 8; ++c)
        #pragma unroll
        for (int j = 0; j < 2; ++j) {
            acc[c][j][0] = __expf(acc[c][j][0] - m0);
            acc[c][j][1] = __expf(acc[c][j][1] - m0);
            acc[c][j][2] = __expf(acc[c][j][2] - m1);
            acc[c][j][3] = __expf(acc[c][j][3] - m1);
            s0 += acc[c][j][0] + acc[c][j][1];
            s1 += acc[c][j][2] + acc[c][j][3];
        }
    s0 += __shfl_xor_sync(~0u, s0, 1);
    s0 += __shfl_xor_sync(~0u, s0, 2);
    s1 += __shfl_xor_sync(~0u, s1, 1);
    s1 += __shfl_xor_sync(~0u, s1, 2);
    if ((lane & 3) == 0) {
        red_sum[R0 * 8 + wn] = s0;
        red_sum[R1 * 8 + wn] = s1;
    }
    __syncthreads();
    s0 = 0.f; s1 = 0.f;
    #pragma unroll
    for (int i = 0; i < 8; ++i) {
        s0 += red_sum[R0 * 8 + i];
        s1 += red_sum[R1 * 8 + i];
    }
    float inv0 = 1.0f / s0, inv1 = 1.0f / s1;

    float* Wb = Wt + ((size_t)bh * SEQ + i0) * SEQ;
    #pragma unroll
    for (int c = 0; c < 8; ++c)
        #pragma unroll
        for (int j = 0; j < 2; ++j) {
            int col = c * 128 + wn * 16 + j * 8 + (lane & 3) * 2;
            *(float2*)&Wb[(size_t)R0 * SEQ + col] =
                make_float2(acc[c][j][0] * inv0, acc[c][j][1] * inv0);
            *(float2*)&Wb[(size_t)R1 * SEQ + col] =
                make_float2(acc[c][j][2] * inv1, acc[c][j][3] * inv1);
        }
}

// ---------------------------------------------------------------------------
// O = P @ V. 128x64 tile, 4x2 warp grid (warp 32x32), 2 CTAs/SM.
// fp32 P via LDG+split pipeline, VT via cp.async.
// ---------------------------------------------------------------------------
#define AV_ATILE 10240                 // 128*80
#define AV_BTILE 5120                  // 64*80
#define AV_ASTG  (2 * AV_ATILE)
#define AV_BSTG  (2 * AV_BTILE)
#define AV_B0    (2 * AV_ASTG)         // 40960
#define AV_SMEM  (2 * AV_ASTG + 2 * AV_BSTG)   // 61440

__global__ __launch_bounds__(256, 2)
void av_mma(const float* __restrict__ Wt) {
    extern __shared__ char sm[];
    const int tid = threadIdx.x;
    const int lane = tid & 31;
    const int warp = tid >> 5;
    const int wm = warp >> 1, wn = warp & 1;     // 4 x 2; warp tile 32x32
    const int bh = blockIdx.y;
    const int b = bh / NHEAD, h = bh - b * NHEAD;
    const size_t m0 = (size_t)blockIdx.x * 128;
    const uint32_t smb = smem_u32(sm);
    const float* P = Wt + ((size_t)bh * SEQ + m0) * SEQ;
    const __nv_bfloat16* Bh = g_VTh + (size_t)bh * HDIM * SEQ;
    const __nv_bfloat16* Bl = g_VTl + (size_t)bh * HDIM * SEQ;

    float acc[2][4][4];
    #pragma unroll
    for (int i = 0; i < 2; ++i)
        #pragma unroll
        for (int j = 0; j < 4; ++j)
            #pragma unroll
            for (int q = 0; q < 4; ++q) acc[i][j][q] = 0.f;

    const int ar = tid >> 3, aj = tid & 7;       // A: rows ar+32g, col aj*4

    auto issueB = [&](int s, int st) {
        const int k0 = s * 32;
        int r = tid >> 2, j = tid & 3;
        if (r < 64) {
            uint32_t d = smb + AV_B0 + st * AV_BSTG + r * 80 + j * 16;
            CP_ASYNC16(d,            Bh + (size_t)r * SEQ + k0 + j * 8);
            CP_ASYNC16(d + AV_BTILE, Bl + (size_t)r * SEQ + k0 + j * 8);
        }
        CP_COMMIT();
    };

    float4 areg[4];
    auto ldgA = [&](int s) {
        const int k0 = s * 32;
        #pragma unroll
        for (int g = 0; g < 4; ++g)
            areg[g] = *(const float4*)&P[(size_t)(ar + 32 * g) * SEQ + k0 + aj * 4];
    };

    const int a_row_l = (lane & 15);
    const int a_col_l = (lane >> 4) << 3;
    const int b_row_l = (lane & 7) + ((lane >> 4) << 3);
    const int b_col_l = ((lane >> 3) & 1) << 3;

    issueB(0, 0);
    issueB(1, 1);
    ldgA(0);
    for (int s = 0; s < 32; ++s) {
        {
            const uint32_t ab = smb + (s & 1) * AV_ASTG;
            #pragma unroll
            for (int g = 0; g < 4; ++g) {
                float4 v = areg[g];
                __nv_bfloat162 lo0, lo1;
                __nv_bfloat162 hi0 = split_hi2(v.x, v.y, lo0);
                __nv_bfloat162 hi1 = split_hi2(v.z, v.w, lo1);
                uint32_t off = (ab - smb) + (ar + 32 * g) * 80 + aj * 8;
                *(__nv_bfloat162*)(sm + off)                = hi0;
                *(__nv_bfloat162*)(sm + off + 4)            = hi1;
                *(__nv_bfloat162*)(sm + off + AV_ATILE)     = lo0;
                *(__nv_bfloat162*)(sm + off + AV_ATILE + 4) = lo1;
            }
        }
        if (s < 31) CP_WAIT1(); else CP_WAIT0();
        __syncthreads();
        if (s + 1 < 32) ldgA(s + 1);

        const uint32_t ab = smb + (s & 1) * AV_ASTG;
        const uint32_t tAh = ab, tAl = ab + AV_ATILE;
        const uint32_t bb = smb + AV_B0 + (s & 1) * AV_BSTG;
        const uint32_t tBh = bb, tBl = bb + AV_BTILE;
        #pragma unroll
        for (int ks = 0; ks < 2; ++ks) {
            uint32_t ah[2][4], al[2][4], bh2[4][2], bl2[4][2];
            #pragma unroll
            for (int mi = 0; mi < 2; ++mi) {
                uint32_t off = (uint32_t)((wm * 32 + mi * 16 + a_row_l) * 80 +
                                          (ks * 16 + a_col_l) * 2);
                LDSM_X4(ah[mi][0], ah[mi][1], ah[mi][2], ah[mi][3], tAh + off);
                LDSM_X4(al[mi][0], al[mi][1], al[mi][2], al[mi][3], tAl + off);
            }
            #pragma unroll
            for (int nj = 0; nj < 2; ++nj) {
                uint32_t off = (uint32_t)((wn * 32 + nj * 16 + b_row_l) * 80 +
                                          (ks * 16 + b_col_l) * 2);
                uint32_t t0, t1, t2, t3;
                LDSM_X4(t0, t1, t2, t3, tBh + off);
                bh2[nj * 2][0] = t0; bh2[nj * 2][1] = t1;
                bh2[nj * 2 + 1][0] = t2; bh2[nj * 2 + 1][1] = t3;
                LDSM_X4(t0, t1, t2, t3, tBl + off);
                bl2[nj * 2][0] = t0; bl2[nj * 2][1] = t1;
                bl2[nj * 2 + 1][0] = t2; bl2[nj * 2 + 1][1] = t3;
            }
            #pragma unroll
            for (int mi = 0; mi < 2; ++mi)
                #pragma unroll
                for (int ni = 0; ni < 4; ++ni) {
                    MMA16816(acc[mi][ni], ah[mi], bh2[ni]);
                    MMA16816(acc[mi][ni], al[mi], bh2[ni]);
                    MMA16816(acc[mi][ni], ah[mi], bl2[ni]);
                }
        }
        __syncthreads();
        if (s + 2 < 32) issueB(s + 2, (s) & 1);
    }

    #pragma unroll
    for (int mi = 0; mi < 2; ++mi) {
        #pragma unroll
        for (int ni = 0; ni < 4; ++ni) {
            int rl = wm * 32 + mi * 16 + (lane >> 2);
            int cl = wn * 32 + ni * 8 + (lane & 3) * 2;
            size_t r = (size_t)b * SEQ + m0 + rl;
            size_t c = h * HDIM + cl;
            __nv_bfloat162 lo0, lo1;
            __nv_bfloat162 hi0 = split_hi2(acc[mi][ni][0], acc[mi][ni][1], lo0);
            __nv_bfloat162 hi1 = split_hi2(acc[mi][ni][2], acc[mi][ni][3], lo1);
            *(__nv_bfloat162*)&g_Oh[r * DIM + c] = hi0;
            *(__nv_bfloat162*)&g_Ol[r * DIM + c] = lo0;
            *(__nv_bfloat162*)&g_Oh[(r + 8) * DIM + c] = hi1;
            *(__nv_bfloat162*)&g_Ol[(r + 8) * DIM + c] = lo1;
        }
    }
}

// ---------------------------------------------------------------------------
extern "C" void kernel_launch(void* const* d_in, const int* in_sizes, int n_in,
                              void* d_out, int out_size) {
    const float* x  = (const float*)d_in[0];
    const float* Wq = (const float*)d_in[1];
    const float* bq = (const float*)d_in[2];
    const float* Wk = (const float*)d_in[3];
    const float* bk = (const float*)d_in[4];
    const float* Wv = (const float*)d_in[5];
    const float* bv = (const float*)d_in[6];
    const float* Wo = (const float*)d_in[7];
    const float* bo = (const float*)d_in[8];

    float* out = (float*)d_out;
    float* wts = out + OUT_OFF;

    cudaFuncSetAttribute(gemm_qkv,
                         cudaFuncAttributeMaxDynamicSharedMemorySize, GSMEM3S);
    cudaFuncSetAttribute(gemm_oproj,
                         cudaFuncAttributeMaxDynamicSharedMemorySize, GSMEM3S);
    cudaFuncSetAttribute(attn_fused,
                         cudaFuncAttributeMaxDynamicSharedMemorySize, AF_SMEM);
    cudaFuncSetAttribute(av_mma,
                         cudaFuncAttributeMaxDynamicSharedMemorySize, AV_SMEM);

    __nv_bfloat16 *Xh, *Xl, *Oh, *Ol, *WTh, *WTl;
    cudaGetSymbolAddress((void**)&Xh, g_Xh);
    cudaGetSymbolAddress((void**)&Xl, g_Xl);
    cudaGetSymbolAddress((void**)&Oh, g_Oh);
    cudaGetSymbolAddress((void**)&Ol, g_Ol);
    cudaGetSymbolAddress((void**)&WTh, g_WTh);
    cudaGetSymbolAddress((void**)&WTl, g_WTl);

    const int NELEM = MROWS * DIM;
    split_kernel<<<NELEM / 4 / 256, 256>>>(x, Xh, Xl, NELEM / 4);
    splitT4<<<dim3(DIM / 32, DIM / 32, 4), dim3(32, 8)>>>(Wq, Wk, Wv, Wo,
                                                          WTh, WTl);

    gemm_qkv<<<dim3(18, MROWS / 128), 256, GSMEM3S>>>(bq, bk, bv);

    attn_fused<<<dim3(SEQ / 32, BH), 512, AF_SMEM>>>(wts);
    av_mma<<<dim3(SEQ / 128, BH), 256, AV_SMEM>>>(wts);

    gemm_oproj<<<dim3(DIM / 128, MROWS / 128), 256, GSMEM3S>>>(
        Oh, Ol, WTh + 3 * DIM * DIM, WTl + 3 * DIM * DIM, bo, out);
}